// round 1
// baseline (speedup 1.0000x reference)
#include <cuda_runtime.h>
#include <math.h>

// Problem constants
#define B_    128
#define P_    2048      // CL*H*W = 8*16*16
#define NP_   32
#define NC_   10
#define CLO_  16
#define K_    160       // NC_*CLO_

// Scratch (allocation-free: device globals)
__device__ float g_u[(size_t)B_ * P_ * K_];     // 167.8 MB
__device__ float g_bias[(size_t)B_ * P_ * NC_]; // 10.5 MB
__device__ float g_s[B_ * K_];
__device__ float g_v[B_ * K_];

// ---------------------------------------------------------------------------
// Zero bias and s
// ---------------------------------------------------------------------------
__global__ void k_init() {
    const size_t nb = (size_t)B_ * P_ * NC_;
    for (size_t i = (size_t)blockIdx.x * blockDim.x + threadIdx.x; i < nb;
         i += (size_t)gridDim.x * blockDim.x) {
        g_bias[i] = 0.f;
        if (i < B_ * K_) g_s[i] = 0.f;
    }
}

// ---------------------------------------------------------------------------
// K1: u[b,p,t] = sum_n squash(tensor)[b,p,n] * W[p,n,t]
// One block per p (2048 blocks, 160 threads). W column t kept in registers,
// x tile (128 b x 32 n) squashed in shared memory, float4 broadcast reads.
// ---------------------------------------------------------------------------
__global__ __launch_bounds__(160) void k1_compute_u(
    const float* __restrict__ tensor, const float* __restrict__ weight) {
    const int p = blockIdx.x;
    const int t = threadIdx.x;

    __shared__ float xs[B_][36];     // pad 36: float4-aligned, low conflicts
    __shared__ float scale_s[B_];

    // load x tile
    for (int idx = t; idx < B_ * NP_; idx += 160) {
        int b = idx >> 5, n = idx & 31;
        xs[b][n] = tensor[(size_t)b * P_ * NP_ + (size_t)p * NP_ + n];
    }
    __syncthreads();

    // squash scale per b: ss/( (1+ss)*sqrt(ss) )
    if (t < B_) {
        float ss = 0.f;
#pragma unroll
        for (int n = 0; n < NP_; n++) { float v = xs[t][n]; ss += v * v; }
        scale_s[t] = ss / ((1.f + ss) * sqrtf(ss));
    }
    __syncthreads();
    for (int idx = t; idx < B_ * NP_; idx += 160) {
        int b = idx >> 5, n = idx & 31;
        xs[b][n] *= scale_s[b];
    }
    __syncthreads();

    // W column t -> registers
    float w[NP_];
    const float* wp = weight + (size_t)p * NP_ * K_ + t;
#pragma unroll
    for (int n = 0; n < NP_; n++) w[n] = wp[(size_t)n * K_];

    // u[b,p,t] for all b
    for (int b = 0; b < B_; b++) {
        const float4* xr = reinterpret_cast<const float4*>(&xs[b][0]);
        float acc = 0.f;
#pragma unroll
        for (int q = 0; q < 8; q++) {
            float4 x4 = xr[q];
            acc = fmaf(w[4 * q + 0], x4.x, acc);
            acc = fmaf(w[4 * q + 1], x4.y, acc);
            acc = fmaf(w[4 * q + 2], x4.z, acc);
            acc = fmaf(w[4 * q + 3], x4.w, acc);
        }
        g_u[((size_t)b * P_ + p) * K_ + t] = acc;
    }
}

// ---------------------------------------------------------------------------
// Routing pass. FIRST: c uniform (=0.1). Otherwise: bias += u.v_prev,
// c = softmax(bias) over NC, acc += c*u. Block: 320 threads = 2 p-slots,
// 32 p per block, grid (P/32, B).
// ---------------------------------------------------------------------------
template <bool FIRST>
__global__ __launch_bounds__(320) void k_route() {
    const int b = blockIdx.y;
    const int p0 = blockIdx.x * 32;
    const int t = threadIdx.x;
    const int slot = t / K_;        // 0..1
    const int tt = t - slot * K_;   // 0..159
    const int n = tt >> 4;          // 0..9
    const int k = tt & 15;

    __shared__ float sm_a[2][NC_];
    __shared__ float sm_e[2][NC_];

    float vreg = FIRST ? 0.f : g_v[b * K_ + tt];
    float acc = 0.f;

    for (int pi = 0; pi < 32; pi += 2) {
        const int p = p0 + pi + slot;
        const float uval = g_u[((size_t)b * P_ + p) * K_ + tt];
        if (FIRST) {
            acc += uval;
        } else {
            // dot over CLO within aligned 16-lane group
            float a = uval * vreg;
            a += __shfl_xor_sync(0xffffffffu, a, 1);
            a += __shfl_xor_sync(0xffffffffu, a, 2);
            a += __shfl_xor_sync(0xffffffffu, a, 4);
            a += __shfl_xor_sync(0xffffffffu, a, 8);

            if (k == 0) {
                const size_t bidx = ((size_t)b * P_ + p) * NC_ + n;
                float biasv = g_bias[bidx] + a;
                g_bias[bidx] = biasv;
                sm_a[slot][n] = biasv;
            }
            __syncthreads();
            if (k == 0) {
                float m = sm_a[slot][0];
#pragma unroll
                for (int j = 1; j < NC_; j++) m = fmaxf(m, sm_a[slot][j]);
                sm_e[slot][n] = __expf(sm_a[slot][n] - m);
            }
            __syncthreads();
            float denom = 0.f;
#pragma unroll
            for (int j = 0; j < NC_; j++) denom += sm_e[slot][j];
            const float c = sm_e[slot][n] / denom;
            acc = fmaf(c, uval, acc);
        }
    }
    if (FIRST) acc *= (1.0f / NC_);
    atomicAdd(&g_s[b * K_ + tt], acc);
}

// ---------------------------------------------------------------------------
// v = squash(s) along CLO (groups of 16, warp-aligned). Optionally re-zero s
// for the next routing pass, optionally emit to output.
// ---------------------------------------------------------------------------
__global__ __launch_bounds__(256) void k_squash(float* __restrict__ out,
                                                int zero_s) {
    const int idx = blockIdx.x * blockDim.x + threadIdx.x;
    if (idx >= B_ * K_) return;
    const float sv = g_s[idx];
    float ss = sv * sv;
    ss += __shfl_xor_sync(0xffffffffu, ss, 1);
    ss += __shfl_xor_sync(0xffffffffu, ss, 2);
    ss += __shfl_xor_sync(0xffffffffu, ss, 4);
    ss += __shfl_xor_sync(0xffffffffu, ss, 8);
    const float scale = ss / ((1.f + ss) * sqrtf(ss));
    const float vv = sv * scale;
    g_v[idx] = vv;
    if (out) out[idx] = vv;
    if (zero_s) g_s[idx] = 0.f;
}

// ---------------------------------------------------------------------------
extern "C" void kernel_launch(void* const* d_in, const int* in_sizes, int n_in,
                              void* d_out, int out_size) {
    const float* tensor = (const float*)d_in[0];
    const float* weight = (const float*)d_in[1];
    float* out = (float*)d_out;

    k_init<<<1024, 256>>>();
    k1_compute_u<<<P_, 160>>>(tensor, weight);

    dim3 rg(P_ / 32, B_);
    // iter 0: uniform c
    k_route<true><<<rg, 320>>>();
    k_squash<<<(B_ * K_ + 255) / 256, 256>>>(nullptr, 1);
    // iter 1
    k_route<false><<<rg, 320>>>();
    k_squash<<<(B_ * K_ + 255) / 256, 256>>>(nullptr, 1);
    // iter 2
    k_route<false><<<rg, 320>>>();
    k_squash<<<(B_ * K_ + 255) / 256, 256>>>(out, 0);
}

// round 2
// speedup vs baseline: 1.8788x; 1.8788x over previous
#include <cuda_runtime.h>
#include <cuda_fp16.h>
#include <math.h>

// Problem constants
#define B_    128
#define P_    2048      // CL*H*W = 8*16*16
#define NP_   32
#define NC_   10
#define CLO_  16
#define K_    160       // NC_*CLO_

// Scratch (allocation-free: device globals)
__device__ __half g_u[(size_t)B_ * P_ * K_];    // 83.9 MB (fp16)
__device__ float  g_bias[(size_t)B_ * P_ * NC_];
__device__ float  g_s[B_ * K_];
__device__ float  g_v[B_ * K_];

// ---------------------------------------------------------------------------
__global__ void k_init_s() {
    int i = blockIdx.x * blockDim.x + threadIdx.x;
    if (i < B_ * K_) g_s[i] = 0.f;
}

// ---------------------------------------------------------------------------
// Packed f32x2 helpers
// ---------------------------------------------------------------------------
__device__ __forceinline__ unsigned long long pack2(float lo, float hi) {
    unsigned long long r;
    asm("mov.b64 %0, {%1, %2};" : "=l"(r) : "f"(lo), "f"(hi));
    return r;
}
__device__ __forceinline__ void unpack2(unsigned long long v, float& lo, float& hi) {
    asm("mov.b64 {%0, %1}, %2;" : "=f"(lo), "=f"(hi) : "l"(v));
}
__device__ __forceinline__ void fma2(unsigned long long& d,
                                     unsigned long long a,
                                     unsigned long long b) {
    asm("fma.rn.f32x2 %0, %1, %2, %0;" : "+l"(d) : "l"(a), "l"(b));
}

// ---------------------------------------------------------------------------
// K1: u[b,p,t] = sum_n squash(tensor)[b,p,n] * W[p,n,t], stored as fp16.
// One block per p, 160 threads (one per t). Processes 2 batches per FFMA2.
// ---------------------------------------------------------------------------
__global__ __launch_bounds__(160) void k1_compute_u(
    const float* __restrict__ tensor, const float* __restrict__ weight) {
    const int p = blockIdx.x;
    const int t = threadIdx.x;

    __shared__ float  xs[B_][NP_];          // 16 KB raw x
    __shared__ float  scale_s[B_];
    __shared__ float2 xsp[B_ / 2][NP_];     // 16 KB paired, squash-scaled

    // load x tile
    for (int idx = t; idx < B_ * NP_; idx += 160) {
        int b = idx >> 5, n = idx & 31;
        xs[b][n] = tensor[(size_t)b * P_ * NP_ + (size_t)p * NP_ + n];
    }
    __syncthreads();

    if (t < B_) {
        float ss = 0.f;
#pragma unroll
        for (int n = 0; n < NP_; n++) { float v = xs[t][n]; ss += v * v; }
        scale_s[t] = ss / ((1.f + ss) * sqrtf(ss));
    }
    __syncthreads();

    // build paired, scaled x: xsp[b2][n] = (x[2b2][n]*sc, x[2b2+1][n]*sc)
    for (int idx = t; idx < (B_ / 2) * NP_; idx += 160) {
        int b2 = idx >> 5, n = idx & 31;
        xsp[b2][n] = make_float2(xs[2 * b2][n] * scale_s[2 * b2],
                                 xs[2 * b2 + 1][n] * scale_s[2 * b2 + 1]);
    }
    __syncthreads();

    // W column t -> duplicated register pairs
    unsigned long long wp[NP_];
    const float* wcol = weight + (size_t)p * NP_ * K_ + t;
#pragma unroll
    for (int n = 0; n < NP_; n++) {
        float wv = wcol[(size_t)n * K_];
        wp[n] = pack2(wv, wv);
    }

    // 2 batches per iteration
    for (int b2 = 0; b2 < B_ / 2; b2++) {
        const float4* xr = reinterpret_cast<const float4*>(&xsp[b2][0]);
        unsigned long long acc = 0ull;
#pragma unroll
        for (int q = 0; q < NP_ / 2; q++) {
            float4 x4 = xr[q];
            fma2(acc, wp[2 * q + 0], pack2(x4.x, x4.y));
            fma2(acc, wp[2 * q + 1], pack2(x4.z, x4.w));
        }
        float a0, a1;
        unpack2(acc, a0, a1);
        g_u[((size_t)(2 * b2) * P_ + p) * K_ + t]     = __float2half(a0);
        g_u[((size_t)(2 * b2 + 1) * P_ + p) * K_ + t] = __float2half(a1);
    }
}

// ---------------------------------------------------------------------------
// Routing pass, warp-autonomous (no block sync in hot loop).
// Each 16-lane half-warp owns one p at a time; lane = one k (0..15);
// the 10 output capsules live in registers. Grid (P/64, B), 256 threads.
// FIRST: c uniform (0.1). READ_BIAS/WRITE_BIAS control bias traffic:
//   iter1: READ=false (bias provably 0), WRITE=true
//   iter2: READ=true, WRITE=false (bias never consumed again)
// ---------------------------------------------------------------------------
template <bool FIRST, bool READ_BIAS, bool WRITE_BIAS>
__global__ __launch_bounds__(256) void k_route() {
    const int b    = blockIdx.y;
    const int warp = threadIdx.x >> 5;
    const int lane = threadIdx.x & 31;
    const int half = lane >> 4;
    const int k    = lane & 15;
    const int p_base = blockIdx.x * 64 + warp * 8;

    __shared__ float s_acc[K_];
    if (threadIdx.x < K_) s_acc[threadIdx.x] = 0.f;
    __syncthreads();

    float vv[NC_];
    if (!FIRST) {
#pragma unroll
        for (int n = 0; n < NC_; n++) vv[n] = g_v[b * K_ + n * 16 + k];
    }
    float acc[NC_];
#pragma unroll
    for (int n = 0; n < NC_; n++) acc[n] = 0.f;

#pragma unroll
    for (int it = 0; it < 4; it++) {
        const int p = p_base + it * 2 + half;
        const __half* up = g_u + ((size_t)b * P_ + p) * K_ + k;
        float uu[NC_];
#pragma unroll
        for (int n = 0; n < NC_; n++) uu[n] = __half2float(up[n * 16]);

        if (FIRST) {
#pragma unroll
            for (int n = 0; n < NC_; n++) acc[n] += uu[n];
        } else {
            // per-capsule dot over CLO=16 via shfl within the 16-lane group
            float a[NC_];
#pragma unroll
            for (int n = 0; n < NC_; n++) {
                float x = uu[n] * vv[n];
                x += __shfl_xor_sync(0xffffffffu, x, 1);
                x += __shfl_xor_sync(0xffffffffu, x, 2);
                x += __shfl_xor_sync(0xffffffffu, x, 4);
                x += __shfl_xor_sync(0xffffffffu, x, 8);
                a[n] = x;
            }
            float braw = 0.f;
            if (READ_BIAS && k < NC_)
                braw = g_bias[((size_t)b * P_ + p) * NC_ + k];

            float bias_n[NC_];
            float m = -1e30f;
#pragma unroll
            for (int n = 0; n < NC_; n++) {
                float bn = a[n];
                if (READ_BIAS)
                    bn += __shfl_sync(0xffffffffu, braw, half * 16 + n);
                bias_n[n] = bn;
                m = fmaxf(m, bn);
            }
            if (WRITE_BIAS && k < NC_) {
                float myb = 0.f;
#pragma unroll
                for (int n = 0; n < NC_; n++)
                    if (k == n) myb = bias_n[n];
                g_bias[((size_t)b * P_ + p) * NC_ + k] = myb;
            }
            float e[NC_], denom = 0.f;
#pragma unroll
            for (int n = 0; n < NC_; n++) {
                e[n] = __expf(bias_n[n] - m);
                denom += e[n];
            }
            const float inv = 1.f / denom;
#pragma unroll
            for (int n = 0; n < NC_; n++)
                acc[n] = fmaf(e[n] * inv, uu[n], acc[n]);
        }
    }

    // combine the two halves (same (n,k), different p) and fold into shared
#pragma unroll
    for (int n = 0; n < NC_; n++) {
        float x = acc[n] + __shfl_xor_sync(0xffffffffu, acc[n], 16);
        if (FIRST) x *= (1.0f / NC_);
        if (half == 0) atomicAdd(&s_acc[n * 16 + k], x);
    }
    __syncthreads();
    if (threadIdx.x < K_)
        atomicAdd(&g_s[b * K_ + threadIdx.x], s_acc[threadIdx.x]);
}

// ---------------------------------------------------------------------------
// v = squash(s) along CLO (groups of 16, warp-aligned). Re-zeroes s for the
// next pass when requested; emits to output on the final call.
// ---------------------------------------------------------------------------
__global__ __launch_bounds__(256) void k_squash(float* __restrict__ out,
                                                int zero_s) {
    const int idx = blockIdx.x * blockDim.x + threadIdx.x;
    if (idx >= B_ * K_) return;
    const float sv = g_s[idx];
    float ss = sv * sv;
    ss += __shfl_xor_sync(0xffffffffu, ss, 1);
    ss += __shfl_xor_sync(0xffffffffu, ss, 2);
    ss += __shfl_xor_sync(0xffffffffu, ss, 4);
    ss += __shfl_xor_sync(0xffffffffu, ss, 8);
    const float scale = ss / ((1.f + ss) * sqrtf(ss));
    const float vv = sv * scale;
    g_v[idx] = vv;
    if (out) out[idx] = vv;
    if (zero_s) g_s[idx] = 0.f;
}

// ---------------------------------------------------------------------------
extern "C" void kernel_launch(void* const* d_in, const int* in_sizes, int n_in,
                              void* d_out, int out_size) {
    const float* tensor = (const float*)d_in[0];
    const float* weight = (const float*)d_in[1];
    float* out = (float*)d_out;

    k_init_s<<<(B_ * K_ + 255) / 256, 256>>>();
    k1_compute_u<<<P_, 160>>>(tensor, weight);

    dim3 rg(P_ / 64, B_);
    // iter 0: uniform c
    k_route<true, false, false><<<rg, 256>>>();
    k_squash<<<(B_ * K_ + 255) / 256, 256>>>(nullptr, 1);
    // iter 1: bias is provably zero on entry -> skip read, write it
    k_route<false, false, true><<<rg, 256>>>();
    k_squash<<<(B_ * K_ + 255) / 256, 256>>>(nullptr, 1);
    // iter 2: read bias, never write (not consumed again)
    k_route<false, true, false><<<rg, 256>>>();
    k_squash<<<(B_ * K_ + 255) / 256, 256>>>(out, 0);
}

// round 3
// speedup vs baseline: 1.9722x; 1.0497x over previous
#include <cuda_runtime.h>
#include <cuda_fp16.h>
#include <math.h>

// Problem constants
#define B_    128
#define P_    2048      // CL*H*W
#define NP_   32
#define NC_   10
#define CLO_  16
#define K_    160       // NC_*CLO_

// Route kernel geometry
#define RT_THREADS 256
#define RT_GROUPS  16                    // 16-lane groups per block
#define RT_PP      4                     // p's per group
#define RT_PBLK    (RT_GROUPS * RT_PP)   // 64 p per block
#define RT_GRIDX   (P_ / RT_PBLK)        // 32 blocks per b

// Scratch (allocation-free: device globals)
__device__ __half g_u[(size_t)B_ * P_ * K_];    // 83.9 MB fp16, layout [b][p][n][k]
__device__ float  g_bias[(size_t)B_ * P_ * NC_];
__device__ float  g_s[B_ * K_];
__device__ float  g_v[B_ * K_];
__device__ int    g_cnt[B_];                    // zero-init, self-resetting

// ---------------------------------------------------------------------------
// Packed f32x2 helpers (k1)
// ---------------------------------------------------------------------------
__device__ __forceinline__ unsigned long long pack2(float lo, float hi) {
    unsigned long long r;
    asm("mov.b64 %0, {%1, %2};" : "=l"(r) : "f"(lo), "f"(hi));
    return r;
}
__device__ __forceinline__ void unpack2(unsigned long long v, float& lo, float& hi) {
    asm("mov.b64 {%0, %1}, %2;" : "=f"(lo), "=f"(hi) : "l"(v));
}
__device__ __forceinline__ void fma2(unsigned long long& d,
                                     unsigned long long a,
                                     unsigned long long b) {
    asm("fma.rn.f32x2 %0, %1, %2, %0;" : "+l"(d) : "l"(a), "l"(b));
}

// ---------------------------------------------------------------------------
// K1: u[b,p,t] = sum_n squash(tensor)[b,p,n] * W[p,n,t], fp16 out.
// One block per p, 160 threads (one per t), 2 batches per FFMA2.
// Block 0 additionally zeroes g_s.
// ---------------------------------------------------------------------------
__global__ __launch_bounds__(160) void k1_compute_u(
    const float* __restrict__ tensor, const float* __restrict__ weight) {
    const int p = blockIdx.x;
    const int t = threadIdx.x;

    if (blockIdx.x == 0) {
        for (int i = t; i < B_ * K_; i += 160) g_s[i] = 0.f;
    }

    __shared__ float  xs[B_][NP_];
    __shared__ float  scale_s[B_];
    __shared__ float2 xsp[B_ / 2][NP_];

    for (int idx = t; idx < B_ * NP_; idx += 160) {
        int b = idx >> 5, n = idx & 31;
        xs[b][n] = tensor[(size_t)b * P_ * NP_ + (size_t)p * NP_ + n];
    }
    __syncthreads();

    if (t < B_) {
        float ss = 0.f;
#pragma unroll
        for (int n = 0; n < NP_; n++) { float v = xs[t][n]; ss += v * v; }
        scale_s[t] = ss / ((1.f + ss) * sqrtf(ss));
    }
    __syncthreads();

    for (int idx = t; idx < (B_ / 2) * NP_; idx += 160) {
        int b2 = idx >> 5, n = idx & 31;
        xsp[b2][n] = make_float2(xs[2 * b2][n] * scale_s[2 * b2],
                                 xs[2 * b2 + 1][n] * scale_s[2 * b2 + 1]);
    }
    __syncthreads();

    unsigned long long wp[NP_];
    const float* wcol = weight + (size_t)p * NP_ * K_ + t;
#pragma unroll
    for (int n = 0; n < NP_; n++) {
        float wv = wcol[(size_t)n * K_];
        wp[n] = pack2(wv, wv);
    }

    for (int b2 = 0; b2 < B_ / 2; b2++) {
        const float4* xr = reinterpret_cast<const float4*>(&xsp[b2][0]);
        unsigned long long acc = 0ull;
#pragma unroll
        for (int q = 0; q < NP_ / 2; q++) {
            float4 x4 = xr[q];
            fma2(acc, wp[2 * q + 0], pack2(x4.x, x4.y));
            fma2(acc, wp[2 * q + 1], pack2(x4.z, x4.w));
        }
        float a0, a1;
        unpack2(acc, a0, a1);
        g_u[((size_t)(2 * b2) * P_ + p) * K_ + t]     = __float2half(a0);
        g_u[((size_t)(2 * b2 + 1) * P_ + p) * K_ + t] = __float2half(a1);
    }
}

// ---------------------------------------------------------------------------
// Routing pass, thread = (p, n). Each 16-lane group owns one p per j-step;
// lane gl = output capsule (active for gl < 10). u[p][n][0..15] read as 2x
// LDG.128, dot over CLO is thread-local, softmax over n via 8 shfls, 1 exp.
// Epilogue: block reduce -> global atomic -> per-b counter -> last block of
// each b performs squash, writes v (or out), zeroes s, resets counter.
// ---------------------------------------------------------------------------
__device__ __forceinline__ void unpack16(uint4 q0, uint4 q1, float* u) {
    const unsigned* w0 = reinterpret_cast<const unsigned*>(&q0);
    const unsigned* w1 = reinterpret_cast<const unsigned*>(&q1);
#pragma unroll
    for (int i = 0; i < 4; i++) {
        float2 f0 = __half22float2(*reinterpret_cast<const __half2*>(&w0[i]));
        float2 f1 = __half22float2(*reinterpret_cast<const __half2*>(&w1[i]));
        u[2 * i]     = f0.x;  u[2 * i + 1]     = f0.y;
        u[8 + 2 * i] = f1.x;  u[8 + 2 * i + 1] = f1.y;
    }
}

template <bool FIRST, bool READ_BIAS, bool WRITE_BIAS, bool LAST>
__global__ __launch_bounds__(RT_THREADS) void k_route(float* __restrict__ out) {
    const int b   = blockIdx.y;
    const int tid = threadIdx.x;
    const int grp = tid >> 4;                 // 0..15
    const int gl  = tid & 15;                 // capsule lane
    const int nn  = (gl < NC_) ? gl : 0;      // clamped for idle lanes
    const bool act = (gl < NC_);
    const int warp = tid >> 5, lane = tid & 31;

    __shared__ float s_red[RT_THREADS / 32][K_];
    __shared__ int s_done;

    float v[16];
    if (!FIRST) {
        const float4* vp = reinterpret_cast<const float4*>(g_v + b * K_ + nn * 16);
#pragma unroll
        for (int q = 0; q < 4; q++) {
            float4 tv = vp[q];
            v[4 * q] = tv.x; v[4 * q + 1] = tv.y; v[4 * q + 2] = tv.z; v[4 * q + 3] = tv.w;
        }
    }
    float acc[16];
#pragma unroll
    for (int k = 0; k < 16; k++) acc[k] = 0.f;

    const int p_base = blockIdx.x * RT_PBLK;
#pragma unroll
    for (int j = 0; j < RT_PP; j++) {
        const int p = p_base + j * RT_GROUPS + grp;
        const uint4* up = reinterpret_cast<const uint4*>(
            g_u + ((size_t)b * P_ + p) * K_ + nn * 16);
        uint4 q0 = up[0], q1 = up[1];
        float u[16];
        unpack16(q0, q1, u);

        if (FIRST) {
#pragma unroll
            for (int k = 0; k < 16; k++) acc[k] += u[k];
        } else {
            float d = 0.f;
#pragma unroll
            for (int k = 0; k < 16; k++) d = fmaf(u[k], v[k], d);
            if (READ_BIAS && act)
                d += g_bias[((size_t)b * P_ + p) * NC_ + gl];
            if (WRITE_BIAS && act)
                g_bias[((size_t)b * P_ + p) * NC_ + gl] = d;

            float m = act ? d : -1e30f;
            m = fmaxf(m, __shfl_xor_sync(0xffffffffu, m, 1));
            m = fmaxf(m, __shfl_xor_sync(0xffffffffu, m, 2));
            m = fmaxf(m, __shfl_xor_sync(0xffffffffu, m, 4));
            m = fmaxf(m, __shfl_xor_sync(0xffffffffu, m, 8));
            float e = act ? __expf(d - m) : 0.f;
            float den = e;
            den += __shfl_xor_sync(0xffffffffu, den, 1);
            den += __shfl_xor_sync(0xffffffffu, den, 2);
            den += __shfl_xor_sync(0xffffffffu, den, 4);
            den += __shfl_xor_sync(0xffffffffu, den, 8);
            const float c = e / den;
#pragma unroll
            for (int k = 0; k < 16; k++) acc[k] = fmaf(c, u[k], acc[k]);
        }
    }

#pragma unroll
    for (int k = 0; k < 16; k++) {
        if (FIRST) acc[k] *= (1.0f / NC_);
        acc[k] += __shfl_xor_sync(0xffffffffu, acc[k], 16);
    }
    // lanes 0..15 of each warp hold the warp's per-n partial sums
    if (lane < 16 && act) {
#pragma unroll
        for (int k = 0; k < 16; k++) s_red[warp][nn * 16 + k] = acc[k];
    }
    __syncthreads();
    if (tid < K_) {
        float s = 0.f;
#pragma unroll
        for (int w = 0; w < RT_THREADS / 32; w++) s += s_red[w][tid];
        atomicAdd(&g_s[b * K_ + tid], s);
    }
    __threadfence();
    __syncthreads();
    if (tid == 0)
        s_done = (atomicAdd(&g_cnt[b], 1) == RT_GRIDX - 1);
    __syncthreads();
    if (!s_done) return;

    // last block for this b: squash(s) -> v / out, re-zero s, reset counter
    if (tid < K_) {
        float sv = __ldcg(&g_s[b * K_ + tid]);
        float ss = sv * sv;
        ss += __shfl_xor_sync(0xffffffffu, ss, 1);
        ss += __shfl_xor_sync(0xffffffffu, ss, 2);
        ss += __shfl_xor_sync(0xffffffffu, ss, 4);
        ss += __shfl_xor_sync(0xffffffffu, ss, 8);
        const float scale = ss / ((1.f + ss) * sqrtf(ss));
        const float vv = sv * scale;
        if (LAST) {
            out[b * K_ + tid] = vv;
        } else {
            g_v[b * K_ + tid] = vv;
            g_s[b * K_ + tid] = 0.f;
        }
    }
    if (tid == 0) g_cnt[b] = 0;
}

// ---------------------------------------------------------------------------
extern "C" void kernel_launch(void* const* d_in, const int* in_sizes, int n_in,
                              void* d_out, int out_size) {
    const float* tensor = (const float*)d_in[0];
    const float* weight = (const float*)d_in[1];
    float* out = (float*)d_out;

    k1_compute_u<<<P_, 160>>>(tensor, weight);

    dim3 rg(RT_GRIDX, B_);
    // iter 0: uniform coupling
    k_route<true,  false, false, false><<<rg, RT_THREADS>>>(out);
    // iter 1: bias provably zero on entry -> skip read, write it
    k_route<false, false, true,  false><<<rg, RT_THREADS>>>(out);
    // iter 2: read bias, never write; emit output
    k_route<false, true,  false, true ><<<rg, RT_THREADS>>>(out);
}

// round 4
// speedup vs baseline: 2.1397x; 1.0849x over previous
#include <cuda_runtime.h>
#include <cuda_fp16.h>
#include <math.h>

// Problem constants
#define B_    128
#define P_    2048      // CL*H*W
#define NP_   32
#define NC_   10
#define K_    160       // NC_*CLO_

// Route geometry: 32 blocks per batch, 64 p per block
#define RT_BLOCKS_PER_B 32
#define RT_THREADS 256
#define RT_PP 4          // p's per 16-lane group

// Scratch (allocation-free device globals; zero-initialized)
__device__ __half g_u[(size_t)B_ * P_ * K_];    // 83.9 MB fp16, layout [b][p][n][k]
__device__ float  g_s[B_ * K_];
__device__ float  g_v[B_ * K_];
__device__ int    g_cnt[B_];                    // self-resetting completion counters

// ---------------------------------------------------------------------------
// Packed f32x2 helpers (k1)
// ---------------------------------------------------------------------------
__device__ __forceinline__ unsigned long long pack2(float lo, float hi) {
    unsigned long long r;
    asm("mov.b64 %0, {%1, %2};" : "=l"(r) : "f"(lo), "f"(hi));
    return r;
}
__device__ __forceinline__ void unpack2(unsigned long long v, float& lo, float& hi) {
    asm("mov.b64 {%0, %1}, %2;" : "=f"(lo), "=f"(hi) : "l"(v));
}
__device__ __forceinline__ void fma2(unsigned long long& d,
                                     unsigned long long a,
                                     unsigned long long b) {
    asm("fma.rn.f32x2 %0, %1, %2, %0;" : "+l"(d) : "l"(a), "l"(b));
}

// ---------------------------------------------------------------------------
// K1: u[b,p,t] = sum_n squash(tensor)[b,p,n] * W[p,n,t], fp16 out.
// One block per p, 160 threads, 2 batches per FFMA2. Block 0 zeroes g_s.
// ---------------------------------------------------------------------------
__global__ __launch_bounds__(160) void k1_compute_u(
    const float* __restrict__ tensor, const float* __restrict__ weight) {
    const int p = blockIdx.x;
    const int t = threadIdx.x;

    if (blockIdx.x == 0) {
        for (int i = t; i < B_ * K_; i += 160) g_s[i] = 0.f;
    }

    __shared__ float  xs[B_][NP_];
    __shared__ float  scale_s[B_];
    __shared__ float2 xsp[B_ / 2][NP_];

    for (int idx = t; idx < B_ * NP_; idx += 160) {
        int b = idx >> 5, n = idx & 31;
        xs[b][n] = tensor[(size_t)b * P_ * NP_ + (size_t)p * NP_ + n];
    }
    __syncthreads();

    if (t < B_) {
        float ss = 0.f;
#pragma unroll
        for (int n = 0; n < NP_; n++) { float v = xs[t][n]; ss += v * v; }
        scale_s[t] = ss / ((1.f + ss) * sqrtf(ss));
    }
    __syncthreads();

    for (int idx = t; idx < (B_ / 2) * NP_; idx += 160) {
        int b2 = idx >> 5, n = idx & 31;
        xsp[b2][n] = make_float2(xs[2 * b2][n] * scale_s[2 * b2],
                                 xs[2 * b2 + 1][n] * scale_s[2 * b2 + 1]);
    }
    __syncthreads();

    unsigned long long wp[NP_];
    const float* wcol = weight + (size_t)p * NP_ * K_ + t;
#pragma unroll
    for (int n = 0; n < NP_; n++) {
        float wv = wcol[(size_t)n * K_];
        wp[n] = pack2(wv, wv);
    }

    for (int b2 = 0; b2 < B_ / 2; b2++) {
        const float4* xr = reinterpret_cast<const float4*>(&xsp[b2][0]);
        unsigned long long acc = 0ull;
#pragma unroll
        for (int q = 0; q < NP_ / 2; q++) {
            float4 x4 = xr[q];
            fma2(acc, wp[2 * q + 0], pack2(x4.x, x4.y));
            fma2(acc, wp[2 * q + 1], pack2(x4.z, x4.w));
        }
        float a0, a1;
        unpack2(acc, a0, a1);
        g_u[((size_t)(2 * b2) * P_ + p) * K_ + t]     = __float2half(a0);
        g_u[((size_t)(2 * b2 + 1) * P_ + p) * K_ + t] = __float2half(a1);
    }
}

// ---------------------------------------------------------------------------
// Shared epilogue: per-b completion counter; the last block for a given b
// squashes g_s and updates state. MODE 0: g_v = squash(s), zero s (iter 0).
// MODE 1: g_v += squash(s), zero s (iter 1; g_v becomes v0+v1 for the fused
// bias-free iter-2 logit). MODE 2: out = squash(s) (final).
// ---------------------------------------------------------------------------
template <int MODE>
__device__ __forceinline__ void epilogue(int b, int tid, float* __restrict__ out) {
    __shared__ int s_done;
    __threadfence();
    __syncthreads();
    if (tid == 0)
        s_done = (atomicAdd(&g_cnt[b], 1) == RT_BLOCKS_PER_B - 1) ? 1 : 0;
    __syncthreads();
    if (!s_done) return;
    __threadfence();   // acquire side
    if (tid < K_) {
        const float sv = __ldcg(&g_s[b * K_ + tid]);
        float ss = sv * sv;
        ss += __shfl_xor_sync(0xffffffffu, ss, 1);
        ss += __shfl_xor_sync(0xffffffffu, ss, 2);
        ss += __shfl_xor_sync(0xffffffffu, ss, 4);
        ss += __shfl_xor_sync(0xffffffffu, ss, 8);
        const float scale = ss / ((1.f + ss) * sqrtf(ss));
        const float vv = sv * scale;
        if (MODE == 0) {
            g_v[b * K_ + tid] = vv;
            g_s[b * K_ + tid] = 0.f;
        } else if (MODE == 1) {
            g_v[b * K_ + tid] += vv;
            g_s[b * K_ + tid] = 0.f;
        } else {
            out[b * K_ + tid] = vv;
        }
    }
    if (tid == 0) g_cnt[b] = 0;
}

// ---------------------------------------------------------------------------
// Iter 0: s0 = (1/NC) * sum_p u[b,p,:]. Fully coalesced uint4 reads, every
// lane useful, 8 independent loads per thread. 160 threads: chunk=tid%20
// (uint4 within the 320B row), sub=tid/20 (8 p-stripes of 8).
// ---------------------------------------------------------------------------
__global__ __launch_bounds__(160) void k_sum0() {
    const int b = blockIdx.y;
    const int tid = threadIdx.x;
    const int chunk = tid % 20;
    const int sub = tid / 20;
    const int p0 = blockIdx.x * 64 + sub * 8;

    float acc[8];
#pragma unroll
    for (int j = 0; j < 8; j++) acc[j] = 0.f;

#pragma unroll
    for (int i = 0; i < 8; i++) {
        const uint4 q = reinterpret_cast<const uint4*>(
            g_u + ((size_t)b * P_ + p0 + i) * K_)[chunk];
        const __half2* h = reinterpret_cast<const __half2*>(&q);
#pragma unroll
        for (int j = 0; j < 4; j++) {
            float2 f = __half22float2(h[j]);
            acc[2 * j] += f.x;
            acc[2 * j + 1] += f.y;
        }
    }

    __shared__ float s_red[8][K_];
#pragma unroll
    for (int j = 0; j < 8; j++) s_red[sub][chunk * 8 + j] = acc[j];
    __syncthreads();
    if (tid < K_) {
        float s = 0.f;
#pragma unroll
        for (int w = 0; w < 8; w++) s += s_red[w][tid];
        atomicAdd(&g_s[b * K_ + tid], s * (1.0f / NC_));
    }
    epilogue<0>(b, tid, nullptr);
}

// ---------------------------------------------------------------------------
// Routing pass (iters 1 and 2). Thread = (p, n): 16-lane group owns one p per
// j-step; lane gl = capsule (active gl<10). u row read as 2x LDG.128, kept in
// half2; dot u.v done in HFMA2 on packed regs; softmax over n via shfl; acc
// fp32. No bias memory: iter2's logit uses g_v = v0+v1.
// ---------------------------------------------------------------------------
template <bool LAST>
__global__ __launch_bounds__(RT_THREADS, 4) void k_route(float* __restrict__ out) {
    const int b   = blockIdx.y;
    const int tid = threadIdx.x;
    const int grp = tid >> 4;
    const int gl  = tid & 15;
    const int nn  = (gl < NC_) ? gl : 0;
    const bool act = (gl < NC_);
    const int warp = tid >> 5, lane = tid & 31;

    // v (loop-invariant) packed as half2
    __half2 vh[8];
    {
        const float4* vp = reinterpret_cast<const float4*>(g_v + b * K_ + nn * 16);
#pragma unroll
        for (int q = 0; q < 4; q++) {
            float4 t = vp[q];
            vh[2 * q]     = __floats2half2_rn(t.x, t.y);
            vh[2 * q + 1] = __floats2half2_rn(t.z, t.w);
        }
    }

    float acc[16];
#pragma unroll
    for (int k = 0; k < 16; k++) acc[k] = 0.f;

    const int p_base = blockIdx.x * 64;
#pragma unroll
    for (int j = 0; j < RT_PP; j++) {
        const int p = p_base + j * 16 + grp;
        const uint4* up = reinterpret_cast<const uint4*>(
            g_u + ((size_t)b * P_ + p) * K_ + nn * 16);
        uint4 q0 = up[0], q1 = up[1];
        __half2 uh[8];
        {
            const __half2* h0 = reinterpret_cast<const __half2*>(&q0);
            const __half2* h1 = reinterpret_cast<const __half2*>(&q1);
#pragma unroll
            for (int i = 0; i < 4; i++) { uh[i] = h0[i]; uh[4 + i] = h1[i]; }
        }

        // logit d = u . v  (HFMA2 on packed regs, final reduce in fp32)
        __half2 dh = __hmul2(uh[0], vh[0]);
#pragma unroll
        for (int i = 1; i < 8; i++) dh = __hfma2(uh[i], vh[i], dh);
        float2 df = __half22float2(dh);
        float d = df.x + df.y;

        // softmax over output capsules (16-lane group, 10 active)
        float m = act ? d : -1e30f;
        m = fmaxf(m, __shfl_xor_sync(0xffffffffu, m, 1));
        m = fmaxf(m, __shfl_xor_sync(0xffffffffu, m, 2));
        m = fmaxf(m, __shfl_xor_sync(0xffffffffu, m, 4));
        m = fmaxf(m, __shfl_xor_sync(0xffffffffu, m, 8));
        float e = act ? __expf(d - m) : 0.f;
        float den = e;
        den += __shfl_xor_sync(0xffffffffu, den, 1);
        den += __shfl_xor_sync(0xffffffffu, den, 2);
        den += __shfl_xor_sync(0xffffffffu, den, 4);
        den += __shfl_xor_sync(0xffffffffu, den, 8);
        const float c = e / den;

#pragma unroll
        for (int i = 0; i < 8; i++) {
            float2 uf = __half22float2(uh[i]);
            acc[2 * i]     = fmaf(c, uf.x, acc[2 * i]);
            acc[2 * i + 1] = fmaf(c, uf.y, acc[2 * i + 1]);
        }
    }

    // combine the two 16-lane groups (same (n,k), different p)
#pragma unroll
    for (int k = 0; k < 16; k++)
        acc[k] += __shfl_xor_sync(0xffffffffu, acc[k], 16);

    __shared__ float s_red[RT_THREADS / 32][K_];
    if (lane < 16 && act) {
#pragma unroll
        for (int k = 0; k < 16; k++) s_red[warp][nn * 16 + k] = acc[k];
    }
    __syncthreads();
    if (tid < K_) {
        float s = 0.f;
#pragma unroll
        for (int w = 0; w < RT_THREADS / 32; w++) s += s_red[w][tid];
        atomicAdd(&g_s[b * K_ + tid], s);
    }
    epilogue<LAST ? 2 : 1>(b, tid, out);
}

// ---------------------------------------------------------------------------
extern "C" void kernel_launch(void* const* d_in, const int* in_sizes, int n_in,
                              void* d_out, int out_size) {
    const float* tensor = (const float*)d_in[0];
    const float* weight = (const float*)d_in[1];
    float* out = (float*)d_out;

    k1_compute_u<<<P_, 160>>>(tensor, weight);

    dim3 rg(RT_BLOCKS_PER_B, B_);
    k_sum0<<<rg, 160>>>();                       // iter 0 (uniform c) + squash
    k_route<false><<<rg, RT_THREADS>>>(nullptr); // iter 1; g_v <- v0+v1
    k_route<true ><<<rg, RT_THREADS>>>(out);     // iter 2; emit output
}

// round 7
// speedup vs baseline: 2.3316x; 1.0897x over previous
#include <cuda_runtime.h>
#include <cuda_fp16.h>
#include <math.h>

// Problem constants
#define B_    128
#define P_    2048      // CL*H*W
#define NP_   32
#define NC_   10
#define K_    160       // NC_*CLO_

// Route geometry: 16 blocks per batch, 128 p per block
#define RT_BLOCKS_PER_B 16
#define RT_THREADS 256
#define RT_PP 8          // p's per 16-lane group

// Scratch (allocation-free device globals; zero-initialized)
__device__ __half g_u[(size_t)B_ * P_ * K_];    // 83.9 MB fp16, layout [b][p][n][k]
__device__ float  g_s[B_ * K_];
__device__ float  g_v[B_ * K_];
__device__ int    g_cnt[B_];                    // self-resetting completion counters

// ---------------------------------------------------------------------------
// Packed f32x2 helpers
// ---------------------------------------------------------------------------
__device__ __forceinline__ unsigned long long pack2(float lo, float hi) {
    unsigned long long r;
    asm("mov.b64 %0, {%1, %2};" : "=l"(r) : "f"(lo), "f"(hi));
    return r;
}
__device__ __forceinline__ void unpack2(unsigned long long v, float& lo, float& hi) {
    asm("mov.b64 {%0, %1}, %2;" : "=f"(lo), "=f"(hi) : "l"(v));
}
__device__ __forceinline__ void fma2(unsigned long long& d,
                                     unsigned long long a,
                                     unsigned long long b) {
    asm("fma.rn.f32x2 %0, %1, %2, %0;" : "+l"(d) : "l"(a), "l"(b));
}

// ---------------------------------------------------------------------------
// K1: u[b,p,t] = sum_n squash(tensor)[b,p,n] * W[p,n,t], fp16 out.
// One block per p, 160 threads (one per t). xsp in smem is pre-packed f32x2;
// inner loop = 16 LDS.128 + 32 FFMA2 (dual accumulators, zero pack movs).
// u halves staged in smem, flushed as coalesced uint4 every 16 batches.
// Block 0 zeroes g_s.
// ---------------------------------------------------------------------------
__global__ __launch_bounds__(160) void k1_compute_u(
    const float* __restrict__ tensor, const float* __restrict__ weight) {
    const int p = blockIdx.x;
    const int t = threadIdx.x;

    if (blockIdx.x == 0) {
        for (int i = t; i < B_ * K_; i += 160) g_s[i] = 0.f;
    }

    __shared__ __align__(16) float4 xs4[B_][NP_ / 4];   // 16 KB raw x
    __shared__ float scale_s[B_];
    __shared__ __align__(16) float2 xsp[B_ / 2][NP_];   // 16 KB packed pairs
    __shared__ __align__(16) __half ustage[16][K_];     // 5 KB store staging

    // load x tile (fully coalesced float4)
    for (int idx = t; idx < B_ * (NP_ / 4); idx += 160) {
        int b = idx >> 3, q = idx & 7;
        xs4[b][q] = reinterpret_cast<const float4*>(
            tensor + (size_t)b * P_ * NP_ + (size_t)p * NP_)[q];
    }
    __syncthreads();

    if (t < B_) {
        float ss = 0.f;
#pragma unroll
        for (int q = 0; q < NP_ / 4; q++) {
            float4 v = xs4[t][q];
            ss += v.x * v.x + v.y * v.y + v.z * v.z + v.w * v.w;
        }
        scale_s[t] = ss / ((1.f + ss) * sqrtf(ss));
    }
    __syncthreads();

    // xsp[b2][n] = (x[2b2][n]*s0, x[2b2+1][n]*s1)  == packed f32x2 operand
    for (int idx = t; idx < (B_ / 2) * NP_; idx += 160) {
        int b2 = idx >> 5, n = idx & 31;
        const float* r0 = reinterpret_cast<const float*>(&xs4[2 * b2][0]);
        const float* r1 = reinterpret_cast<const float*>(&xs4[2 * b2 + 1][0]);
        xsp[b2][n] = make_float2(r0[n] * scale_s[2 * b2],
                                 r1[n] * scale_s[2 * b2 + 1]);
    }
    __syncthreads();

    // W column t -> duplicated register pairs
    unsigned long long wp[NP_];
    const float* wcol = weight + (size_t)p * NP_ * K_ + t;
#pragma unroll
    for (int n = 0; n < NP_; n++) {
        float wv = wcol[(size_t)n * K_];
        wp[n] = pack2(wv, wv);
    }

    // 8 chunks x 8 b2 (=16 batches) per chunk, staged store flush per chunk
    for (int chunk = 0; chunk < 8; chunk++) {
#pragma unroll
        for (int bb = 0; bb < 8; bb++) {
            const int b2 = chunk * 8 + bb;
            const ulonglong2* xr =
                reinterpret_cast<const ulonglong2*>(&xsp[b2][0]);
            unsigned long long a0 = 0ull, a1 = 0ull;
#pragma unroll
            for (int q = 0; q < NP_ / 2; q++) {   // 16 iters: covers n = 0..31
                ulonglong2 xq = xr[q];
                fma2(a0, wp[2 * q],     xq.x);
                fma2(a1, wp[2 * q + 1], xq.y);
            }
            float l0, h0, l1, h1;
            unpack2(a0, l0, h0);
            unpack2(a1, l1, h1);
            ustage[2 * bb][t]     = __float2half(l0 + l1);
            ustage[2 * bb + 1][t] = __float2half(h0 + h1);
        }
        __syncthreads();
        // flush 16 rows as uint4 (coalesced)
#pragma unroll
        for (int e = 0; e < 2; e++) {
            int idx = t + e * 160;
            int row = idx / 20, c = idx % 20;
            int b = chunk * 16 + row;
            reinterpret_cast<uint4*>(g_u + ((size_t)b * P_ + p) * K_)[c] =
                reinterpret_cast<const uint4*>(&ustage[row][0])[c];
        }
        __syncthreads();
    }
}

// ---------------------------------------------------------------------------
// Shared epilogue: last block for a given b squashes g_s.
// MODE 0: g_v = squash(s), zero s. MODE 1: g_v += squash(s), zero s
// (g_v becomes v0+v1 -> bias-free iter-2 logit). MODE 2: out = squash(s).
// ---------------------------------------------------------------------------
template <int MODE>
__device__ __forceinline__ void epilogue(int b, int tid, float* __restrict__ out) {
    __shared__ int s_done;
    __threadfence();
    __syncthreads();
    if (tid == 0)
        s_done = (atomicAdd(&g_cnt[b], 1) == RT_BLOCKS_PER_B - 1) ? 1 : 0;
    __syncthreads();
    if (!s_done) return;
    __threadfence();
    if (tid < K_) {
        const float sv = __ldcg(&g_s[b * K_ + tid]);
        float ss = sv * sv;
        ss += __shfl_xor_sync(0xffffffffu, ss, 1);
        ss += __shfl_xor_sync(0xffffffffu, ss, 2);
        ss += __shfl_xor_sync(0xffffffffu, ss, 4);
        ss += __shfl_xor_sync(0xffffffffu, ss, 8);
        const float scale = ss / ((1.f + ss) * sqrtf(ss));
        const float vv = sv * scale;
        if (MODE == 0) {
            g_v[b * K_ + tid] = vv;
            g_s[b * K_ + tid] = 0.f;
        } else if (MODE == 1) {
            g_v[b * K_ + tid] += vv;
            g_s[b * K_ + tid] = 0.f;
        } else {
            out[b * K_ + tid] = vv;
        }
    }
    if (tid == 0) g_cnt[b] = 0;
}

// ---------------------------------------------------------------------------
// Iter 0: s0 = (1/NC) * sum_p u[b,p,:]. Fully coalesced uint4 reads.
// 160 threads: chunk=tid%20, sub=tid/20 -> 8 stripes of 16 p; 128 p/block.
// ---------------------------------------------------------------------------
__global__ __launch_bounds__(160) void k_sum0() {
    const int b = blockIdx.y;
    const int tid = threadIdx.x;
    const int chunk = tid % 20;
    const int sub = tid / 20;
    const int p0 = blockIdx.x * 128 + sub * 16;

    float acc[8];
#pragma unroll
    for (int j = 0; j < 8; j++) acc[j] = 0.f;

#pragma unroll
    for (int i = 0; i < 16; i++) {
        const uint4 q = reinterpret_cast<const uint4*>(
            g_u + ((size_t)b * P_ + p0 + i) * K_)[chunk];
        const __half2* h = reinterpret_cast<const __half2*>(&q);
#pragma unroll
        for (int j = 0; j < 4; j++) {
            float2 f = __half22float2(h[j]);
            acc[2 * j] += f.x;
            acc[2 * j + 1] += f.y;
        }
    }

    __shared__ float s_red[8][K_];
#pragma unroll
    for (int j = 0; j < 8; j++) s_red[sub][chunk * 8 + j] = acc[j];
    __syncthreads();
    if (tid < K_) {
        float s = 0.f;
#pragma unroll
        for (int w = 0; w < 8; w++) s += s_red[w][tid];
        atomicAdd(&g_s[b * K_ + tid], s * (1.0f / NC_));
    }
    epilogue<0>(b, tid, nullptr);
}

// ---------------------------------------------------------------------------
// Routing pass (iters 1 and 2). Thread = (p, n). Softmax without max
// (logits bounded: |u.v| < ~5), 4 shfls. Acc update in packed f32x2.
// ---------------------------------------------------------------------------
template <bool LAST>
__global__ __launch_bounds__(RT_THREADS, 4) void k_route(float* __restrict__ out) {
    const int b   = blockIdx.y;
    const int tid = threadIdx.x;
    const int grp = tid >> 4;
    const int gl  = tid & 15;
    const int nn  = (gl < NC_) ? gl : 0;
    const bool act = (gl < NC_);
    const int warp = tid >> 5, lane = tid & 31;

    // v (loop-invariant) packed as half2
    __half2 vh[8];
    {
        const float4* vp = reinterpret_cast<const float4*>(g_v + b * K_ + nn * 16);
#pragma unroll
        for (int q = 0; q < 4; q++) {
            float4 t = vp[q];
            vh[2 * q]     = __floats2half2_rn(t.x, t.y);
            vh[2 * q + 1] = __floats2half2_rn(t.z, t.w);
        }
    }

    unsigned long long acc2[8];
#pragma unroll
    for (int i = 0; i < 8; i++) acc2[i] = 0ull;

    const int p_base = blockIdx.x * 128;
#pragma unroll
    for (int j = 0; j < RT_PP; j++) {
        const int p = p_base + j * 16 + grp;
        const uint4* up = reinterpret_cast<const uint4*>(
            g_u + ((size_t)b * P_ + p) * K_ + nn * 16);
        uint4 q0 = up[0], q1 = up[1];
        __half2 uh[8];
        {
            const __half2* h0 = reinterpret_cast<const __half2*>(&q0);
            const __half2* h1 = reinterpret_cast<const __half2*>(&q1);
#pragma unroll
            for (int i = 0; i < 4; i++) { uh[i] = h0[i]; uh[4 + i] = h1[i]; }
        }

        // logit d = u . v  (HFMA2, fp32 finish)
        __half2 dh = __hmul2(uh[0], vh[0]);
#pragma unroll
        for (int i = 1; i < 8; i++) dh = __hfma2(uh[i], vh[i], dh);
        float2 df = __half22float2(dh);
        const float d = df.x + df.y;

        // softmax over capsules, no max (bounded logits)
        float e = act ? __expf(d) : 0.f;
        float den = e;
        den += __shfl_xor_sync(0xffffffffu, den, 1);
        den += __shfl_xor_sync(0xffffffffu, den, 2);
        den += __shfl_xor_sync(0xffffffffu, den, 4);
        den += __shfl_xor_sync(0xffffffffu, den, 8);
        const float c = e / den;

        const unsigned long long c2 = pack2(c, c);
#pragma unroll
        for (int i = 0; i < 8; i++) {
            float2 uf = __half22float2(uh[i]);
            fma2(acc2[i], c2, pack2(uf.x, uf.y));
        }
    }

    float acc[16];
#pragma unroll
    for (int i = 0; i < 8; i++) unpack2(acc2[i], acc[2 * i], acc[2 * i + 1]);

    // combine the two 16-lane groups (same (n,k), different p)
#pragma unroll
    for (int k = 0; k < 16; k++)
        acc[k] += __shfl_xor_sync(0xffffffffu, acc[k], 16);

    __shared__ float s_red[RT_THREADS / 32][K_];
    if (lane < 16 && act) {
#pragma unroll
        for (int k = 0; k < 16; k++) s_red[warp][nn * 16 + k] = acc[k];
    }
    __syncthreads();
    if (tid < K_) {
        float s = 0.f;
#pragma unroll
        for (int w = 0; w < RT_THREADS / 32; w++) s += s_red[w][tid];
        atomicAdd(&g_s[b * K_ + tid], s);
    }
    epilogue<LAST ? 2 : 1>(b, tid, out);
}

// ---------------------------------------------------------------------------
extern "C" void kernel_launch(void* const* d_in, const int* in_sizes, int n_in,
                              void* d_out, int out_size) {
    const float* tensor = (const float*)d_in[0];
    const float* weight = (const float*)d_in[1];
    float* out = (float*)d_out;

    k1_compute_u<<<P_, 160>>>(tensor, weight);

    dim3 rg(RT_BLOCKS_PER_B, B_);
    k_sum0<<<rg, 160>>>();                       // iter 0 (uniform c) + squash
    k_route<false><<<rg, RT_THREADS>>>(nullptr); // iter 1; g_v <- v0+v1
    k_route<true ><<<rg, RT_THREADS>>>(out);     // iter 2; emit output
}

// round 8
// speedup vs baseline: 2.4125x; 1.0347x over previous
#include <cuda_runtime.h>
#include <cuda_fp16.h>
#include <math.h>

// Problem constants
#define B_    128
#define P_    2048      // CL*H*W
#define NP_   32
#define NC_   10
#define K_    160       // NC_*CLO_

// Route geometry: 16 blocks per batch, 128 p per block
#define RT_BLOCKS_PER_B 16
#define RT_THREADS 256

// Scratch (allocation-free device globals; zero-initialized)
__device__ __half g_u[(size_t)B_ * P_ * K_];    // 83.9 MB fp16, layout [b][p][n][k]
__device__ float  g_s[B_ * K_];
__device__ float  g_v[B_ * K_];
__device__ int    g_cnt[B_];                    // self-resetting completion counters

// ---------------------------------------------------------------------------
// Packed f32x2 helpers
// ---------------------------------------------------------------------------
__device__ __forceinline__ unsigned long long pack2(float lo, float hi) {
    unsigned long long r;
    asm("mov.b64 %0, {%1, %2};" : "=l"(r) : "f"(lo), "f"(hi));
    return r;
}
__device__ __forceinline__ void unpack2(unsigned long long v, float& lo, float& hi) {
    asm("mov.b64 {%0, %1}, %2;" : "=f"(lo), "=f"(hi) : "l"(v));
}
__device__ __forceinline__ void fma2(unsigned long long& d,
                                     unsigned long long a,
                                     unsigned long long b) {
    asm("fma.rn.f32x2 %0, %1, %2, %0;" : "+l"(d) : "l"(a), "l"(b));
}

// ---------------------------------------------------------------------------
// K1: u[b,p,t] = sum_n squash(tensor)[b,p,n] * W[p,n,t], fp16 out.
// One block per p, 160 threads (one per t). xsp in smem is pre-packed f32x2;
// inner loop = 16 LDS.128 + 32 FFMA2 (dual accumulators, zero pack movs).
// u halves staged in smem, flushed as coalesced uint4 every 16 batches.
// Block 0 zeroes g_s.
// ---------------------------------------------------------------------------
__global__ __launch_bounds__(160) void k1_compute_u(
    const float* __restrict__ tensor, const float* __restrict__ weight) {
    const int p = blockIdx.x;
    const int t = threadIdx.x;

    if (blockIdx.x == 0) {
        for (int i = t; i < B_ * K_; i += 160) g_s[i] = 0.f;
    }

    __shared__ __align__(16) float4 xs4[B_][NP_ / 4];   // 16 KB raw x
    __shared__ float scale_s[B_];
    __shared__ __align__(16) float2 xsp[B_ / 2][NP_];   // 16 KB packed pairs
    __shared__ __align__(16) __half ustage[16][K_];     // 5 KB store staging

    // load x tile (fully coalesced float4)
    for (int idx = t; idx < B_ * (NP_ / 4); idx += 160) {
        int b = idx >> 3, q = idx & 7;
        xs4[b][q] = reinterpret_cast<const float4*>(
            tensor + (size_t)b * P_ * NP_ + (size_t)p * NP_)[q];
    }
    __syncthreads();

    if (t < B_) {
        float ss = 0.f;
#pragma unroll
        for (int q = 0; q < NP_ / 4; q++) {
            float4 v = xs4[t][q];
            ss += v.x * v.x + v.y * v.y + v.z * v.z + v.w * v.w;
        }
        scale_s[t] = ss / ((1.f + ss) * sqrtf(ss));
    }
    __syncthreads();

    // xsp[b2][n] = (x[2b2][n]*s0, x[2b2+1][n]*s1)  == packed f32x2 operand
    for (int idx = t; idx < (B_ / 2) * NP_; idx += 160) {
        int b2 = idx >> 5, n = idx & 31;
        const float* r0 = reinterpret_cast<const float*>(&xs4[2 * b2][0]);
        const float* r1 = reinterpret_cast<const float*>(&xs4[2 * b2 + 1][0]);
        xsp[b2][n] = make_float2(r0[n] * scale_s[2 * b2],
                                 r1[n] * scale_s[2 * b2 + 1]);
    }
    __syncthreads();

    // W column t -> duplicated register pairs
    unsigned long long wp[NP_];
    const float* wcol = weight + (size_t)p * NP_ * K_ + t;
#pragma unroll
    for (int n = 0; n < NP_; n++) {
        float wv = wcol[(size_t)n * K_];
        wp[n] = pack2(wv, wv);
    }

    // 8 chunks x 8 b2 (=16 batches) per chunk, staged store flush per chunk
    for (int chunk = 0; chunk < 8; chunk++) {
#pragma unroll
        for (int bb = 0; bb < 8; bb++) {
            const int b2 = chunk * 8 + bb;
            const ulonglong2* xr =
                reinterpret_cast<const ulonglong2*>(&xsp[b2][0]);
            unsigned long long a0 = 0ull, a1 = 0ull;
#pragma unroll
            for (int q = 0; q < NP_ / 2; q++) {   // 16 iters: covers n = 0..31
                ulonglong2 xq = xr[q];
                fma2(a0, wp[2 * q],     xq.x);
                fma2(a1, wp[2 * q + 1], xq.y);
            }
            float l0, h0, l1, h1;
            unpack2(a0, l0, h0);
            unpack2(a1, l1, h1);
            ustage[2 * bb][t]     = __float2half(l0 + l1);
            ustage[2 * bb + 1][t] = __float2half(h0 + h1);
        }
        __syncthreads();
        // flush 16 rows as uint4 (coalesced)
#pragma unroll
        for (int e = 0; e < 2; e++) {
            int idx = t + e * 160;
            int row = idx / 20, c = idx % 20;
            int b = chunk * 16 + row;
            reinterpret_cast<uint4*>(g_u + ((size_t)b * P_ + p) * K_)[c] =
                reinterpret_cast<const uint4*>(&ustage[row][0])[c];
        }
        __syncthreads();
    }
}

// ---------------------------------------------------------------------------
// Shared epilogue: last block for a given b squashes g_s.
// MODE 0: g_v = squash(s), zero s. MODE 1: g_v += squash(s), zero s
// (g_v becomes v0+v1 -> bias-free iter-2 logit). MODE 2: out = squash(s).
// ---------------------------------------------------------------------------
template <int MODE>
__device__ __forceinline__ void epilogue(int b, int tid, float* __restrict__ out) {
    __shared__ int s_done;
    __threadfence();
    __syncthreads();
    if (tid == 0)
        s_done = (atomicAdd(&g_cnt[b], 1) == RT_BLOCKS_PER_B - 1) ? 1 : 0;
    __syncthreads();
    if (!s_done) return;
    __threadfence();
    if (tid < K_) {
        const float sv = __ldcg(&g_s[b * K_ + tid]);
        float ss = sv * sv;
        ss += __shfl_xor_sync(0xffffffffu, ss, 1);
        ss += __shfl_xor_sync(0xffffffffu, ss, 2);
        ss += __shfl_xor_sync(0xffffffffu, ss, 4);
        ss += __shfl_xor_sync(0xffffffffu, ss, 8);
        const float scale = ss / ((1.f + ss) * sqrtf(ss));
        const float vv = sv * scale;
        if (MODE == 0) {
            g_v[b * K_ + tid] = vv;
            g_s[b * K_ + tid] = 0.f;
        } else if (MODE == 1) {
            g_v[b * K_ + tid] += vv;
            g_s[b * K_ + tid] = 0.f;
        } else {
            out[b * K_ + tid] = vv;
        }
    }
    if (tid == 0) g_cnt[b] = 0;
}

// ---------------------------------------------------------------------------
// Iter 0: s0 = (1/NC) * sum_p u[b,p,:]. Fully coalesced uint4 reads.
// 160 threads: chunk=tid%20, sub=tid/20 -> 8 stripes of 16 p; 128 p/block.
// ---------------------------------------------------------------------------
__global__ __launch_bounds__(160) void k_sum0() {
    const int b = blockIdx.y;
    const int tid = threadIdx.x;
    const int chunk = tid % 20;
    const int sub = tid / 20;
    const int p0 = blockIdx.x * 128 + sub * 16;

    float acc[8];
#pragma unroll
    for (int j = 0; j < 8; j++) acc[j] = 0.f;

#pragma unroll
    for (int i = 0; i < 16; i++) {
        const uint4 q = reinterpret_cast<const uint4*>(
            g_u + ((size_t)b * P_ + p0 + i) * K_)[chunk];
        const __half2* h = reinterpret_cast<const __half2*>(&q);
#pragma unroll
        for (int j = 0; j < 4; j++) {
            float2 f = __half22float2(h[j]);
            acc[2 * j] += f.x;
            acc[2 * j + 1] += f.y;
        }
    }

    __shared__ float s_red[8][K_];
#pragma unroll
    for (int j = 0; j < 8; j++) s_red[sub][chunk * 8 + j] = acc[j];
    __syncthreads();
    if (tid < K_) {
        float s = 0.f;
#pragma unroll
        for (int w = 0; w < 8; w++) s += s_red[w][tid];
        atomicAdd(&g_s[b * K_ + tid], s * (1.0f / NC_));
    }
    epilogue<0>(b, tid, nullptr);
}

// ---------------------------------------------------------------------------
// Routing pass (iters 1 and 2). Thread = (p, n); each 16-lane group now
// processes TWO p's per j-step with independent register chains (ILP over the
// serial shfl/exp softmax chain). Idle capsule lanes (gl>=10) no longer issue
// duplicate loads (predicated to zero).
// ---------------------------------------------------------------------------
template <bool LAST>
__global__ __launch_bounds__(RT_THREADS) void k_route(float* __restrict__ out) {
    const int b   = blockIdx.y;
    const int tid = threadIdx.x;
    const int grp = tid >> 4;
    const int gl  = tid & 15;
    const int nn  = (gl < NC_) ? gl : 0;
    const bool act = (gl < NC_);
    const int warp = tid >> 5, lane = tid & 31;

    // v (loop-invariant) packed as half2
    __half2 vh[8];
    {
        const float4* vp = reinterpret_cast<const float4*>(g_v + b * K_ + nn * 16);
#pragma unroll
        for (int q = 0; q < 4; q++) {
            float4 t = vp[q];
            vh[2 * q]     = __floats2half2_rn(t.x, t.y);
            vh[2 * q + 1] = __floats2half2_rn(t.z, t.w);
        }
    }

    unsigned long long acc2[8];
#pragma unroll
    for (int i = 0; i < 8; i++) acc2[i] = 0ull;

    const int p_base = blockIdx.x * 128;
#pragma unroll
    for (int j = 0; j < 4; j++) {
        const int p0 = p_base + (2 * j) * 16 + grp;
        const int p1 = p_base + (2 * j + 1) * 16 + grp;

        uint4 qa0 = make_uint4(0, 0, 0, 0), qa1 = qa0, qb0 = qa0, qb1 = qa0;
        if (act) {
            const uint4* ua = reinterpret_cast<const uint4*>(
                g_u + ((size_t)b * P_ + p0) * K_ + nn * 16);
            const uint4* ub = reinterpret_cast<const uint4*>(
                g_u + ((size_t)b * P_ + p1) * K_ + nn * 16);
            qa0 = ua[0]; qa1 = ua[1];
            qb0 = ub[0]; qb1 = ub[1];
        }
        __half2 uha[8], uhb[8];
        {
            const __half2* a0 = reinterpret_cast<const __half2*>(&qa0);
            const __half2* a1 = reinterpret_cast<const __half2*>(&qa1);
            const __half2* b0 = reinterpret_cast<const __half2*>(&qb0);
            const __half2* b1 = reinterpret_cast<const __half2*>(&qb1);
#pragma unroll
            for (int i = 0; i < 4; i++) {
                uha[i] = a0[i]; uha[4 + i] = a1[i];
                uhb[i] = b0[i]; uhb[4 + i] = b1[i];
            }
        }

        // two independent logit dots (HFMA2, fp32 finish)
        __half2 dha = __hmul2(uha[0], vh[0]);
        __half2 dhb = __hmul2(uhb[0], vh[0]);
#pragma unroll
        for (int i = 1; i < 8; i++) {
            dha = __hfma2(uha[i], vh[i], dha);
            dhb = __hfma2(uhb[i], vh[i], dhb);
        }
        float2 dfa = __half22float2(dha);
        float2 dfb = __half22float2(dhb);
        const float da = dfa.x + dfa.y;
        const float db = dfb.x + dfb.y;

        // two interleaved softmax reductions (no max: logits bounded)
        float ea = act ? __expf(da) : 0.f;
        float eb = act ? __expf(db) : 0.f;
        float dena = ea, denb = eb;
        dena += __shfl_xor_sync(0xffffffffu, dena, 1);
        denb += __shfl_xor_sync(0xffffffffu, denb, 1);
        dena += __shfl_xor_sync(0xffffffffu, dena, 2);
        denb += __shfl_xor_sync(0xffffffffu, denb, 2);
        dena += __shfl_xor_sync(0xffffffffu, dena, 4);
        denb += __shfl_xor_sync(0xffffffffu, denb, 4);
        dena += __shfl_xor_sync(0xffffffffu, dena, 8);
        denb += __shfl_xor_sync(0xffffffffu, denb, 8);
        const float ca = ea / dena;
        const float cb = eb / denb;

        const unsigned long long ca2 = pack2(ca, ca);
        const unsigned long long cb2 = pack2(cb, cb);
#pragma unroll
        for (int i = 0; i < 8; i++) {
            float2 ufa = __half22float2(uha[i]);
            float2 ufb = __half22float2(uhb[i]);
            fma2(acc2[i], ca2, pack2(ufa.x, ufa.y));
            fma2(acc2[i], cb2, pack2(ufb.x, ufb.y));
        }
    }

    float acc[16];
#pragma unroll
    for (int i = 0; i < 8; i++) unpack2(acc2[i], acc[2 * i], acc[2 * i + 1]);

    // combine the two 16-lane groups (same (n,k), different p)
#pragma unroll
    for (int k = 0; k < 16; k++)
        acc[k] += __shfl_xor_sync(0xffffffffu, acc[k], 16);

    __shared__ float s_red[RT_THREADS / 32][K_];
    if (lane < 16 && act) {
#pragma unroll
        for (int k = 0; k < 16; k++) s_red[warp][nn * 16 + k] = acc[k];
    }
    __syncthreads();
    if (tid < K_) {
        float s = 0.f;
#pragma unroll
        for (int w = 0; w < RT_THREADS / 32; w++) s += s_red[w][tid];
        atomicAdd(&g_s[b * K_ + tid], s);
    }
    epilogue<LAST ? 2 : 1>(b, tid, out);
}

// ---------------------------------------------------------------------------
extern "C" void kernel_launch(void* const* d_in, const int* in_sizes, int n_in,
                              void* d_out, int out_size) {
    const float* tensor = (const float*)d_in[0];
    const float* weight = (const float*)d_in[1];
    float* out = (float*)d_out;

    k1_compute_u<<<P_, 160>>>(tensor, weight);

    dim3 rg(RT_BLOCKS_PER_B, B_);
    k_sum0<<<rg, 160>>>();                       // iter 0 (uniform c) + squash
    k_route<false><<<rg, RT_THREADS>>>(nullptr); // iter 1; g_v <- v0+v1
    k_route<true ><<<rg, RT_THREADS>>>(out);     // iter 2; emit output
}

// round 10
// speedup vs baseline: 2.9129x; 1.2075x over previous
#include <cuda_runtime.h>
#include <cuda_fp16.h>
#include <math.h>
#include <stdint.h>

// Problem constants
#define B_    128
#define P_    2048      // CL*H*W
#define NP_   32
#define NC_   10
#define K_    160       // NC_*CLO_

// Route geometry: 16 blocks per batch, 128 p per block
#define RT_BLOCKS_PER_B 16
#define RT_THREADS 256

// Scratch (allocation-free device globals; zero-initialized)
__device__ __half g_u[(size_t)B_ * P_ * K_];    // 83.9 MB fp16, layout [b][p][n][k]
__device__ float  g_s[B_ * K_];
__device__ float  g_v[B_ * K_];
__device__ int    g_cnt[B_];                    // self-resetting completion counters

// ---------------------------------------------------------------------------
// Packed f32x2 helpers (route)
// ---------------------------------------------------------------------------
__device__ __forceinline__ unsigned long long pack2(float lo, float hi) {
    unsigned long long r;
    asm("mov.b64 %0, {%1, %2};" : "=l"(r) : "f"(lo), "f"(hi));
    return r;
}
__device__ __forceinline__ void unpack2(unsigned long long v, float& lo, float& hi) {
    asm("mov.b64 {%0, %1}, %2;" : "=f"(lo), "=f"(hi) : "l"(v));
}
__device__ __forceinline__ void fma2(unsigned long long& d,
                                     unsigned long long a,
                                     unsigned long long b) {
    asm("fma.rn.f32x2 %0, %1, %2, %0;" : "+l"(d) : "l"(a), "l"(b));
}

// ---------------------------------------------------------------------------
// K1 (HMMA): per p, D[128 b][160 t] = squash(x)[128 b][32 n] @ W[32 n][160 t]
// via mma.sync.m16n8k16 (fp16 in, fp32 acc). 256 threads = 8 warps; warp w
// owns m-tile rows 16w..16w+15 across 20 n-tiles and 2 k-chunks.
// A smem: [128 b][32 k] fp16, row stride 80B (conflict-free).
// B smem: [160 t][32 k] fp16 (col-major operand), row stride 80B.
// Stage (unioned over A/B after MMA): [128 b][320B], row stride 336B.
// Block 0 zeroes g_s.
// ---------------------------------------------------------------------------
#define SA 80
#define A_OFF 0                       // 128*80 = 10240
#define BOFF  10240                   // 160*80 = 12800, ends 23040
#define SSTG  336
#define SB_BYTES (128 * SSTG)         // 43008 (union covers A+B = 23040)

__device__ __forceinline__ void mma16816(float* c, uint32_t a0, uint32_t a1,
                                         uint32_t a2, uint32_t a3,
                                         uint32_t b0, uint32_t b1) {
    asm volatile(
        "mma.sync.aligned.m16n8k16.row.col.f32.f16.f16.f32 "
        "{%0,%1,%2,%3}, {%4,%5,%6,%7}, {%8,%9}, {%0,%1,%2,%3};"
        : "+f"(c[0]), "+f"(c[1]), "+f"(c[2]), "+f"(c[3])
        : "r"(a0), "r"(a1), "r"(a2), "r"(a3), "r"(b0), "r"(b1));
}

__global__ __launch_bounds__(256) void k1_mma(
    const float* __restrict__ tensor, const float* __restrict__ weight) {
    const int p = blockIdx.x;
    const int tid = threadIdx.x;
    const int wid = tid >> 5;
    const int lane = tid & 31;
    const int gid = lane >> 2;    // 0..7
    const int tig = lane & 3;     // 0..3

    __shared__ __align__(16) unsigned char sb[SB_BYTES];

    if (p == 0) {
        for (int i = tid; i < B_ * K_; i += 256) g_s[i] = 0.f;
    }

    // --- A fill: warp w rows b = 16w+i; lane = n. squash inline. ---
    const float* xbase = tensor + (size_t)p * NP_;
#pragma unroll
    for (int i = 0; i < 16; i++) {
        const int b = wid * 16 + i;
        const float x = xbase[(size_t)b * P_ * NP_ + lane];
        float ss = x * x;
        ss += __shfl_xor_sync(0xffffffffu, ss, 1);
        ss += __shfl_xor_sync(0xffffffffu, ss, 2);
        ss += __shfl_xor_sync(0xffffffffu, ss, 4);
        ss += __shfl_xor_sync(0xffffffffu, ss, 8);
        ss += __shfl_xor_sync(0xffffffffu, ss, 16);
        const float scale = ss / ((1.f + ss) * sqrtf(ss));
        *reinterpret_cast<__half*>(sb + A_OFF + b * SA + lane * 2) =
            __float2half(x * scale);
    }

    // --- B fill: thread owns row t (t=tid<160): Bt[t][k] = W[k][t]. ---
    const float* wbase = weight + (size_t)p * NP_ * K_;
    if (tid < K_) {
        float wv[NP_];
#pragma unroll
        for (int n = 0; n < NP_; n++) wv[n] = wbase[(size_t)n * K_ + tid];
        const int rowbase = BOFF + tid * SA;
#pragma unroll
        for (int j = 0; j < 8; j++) {
            uint2 d;
            __half2 h0 = __floats2half2_rn(wv[4 * j], wv[4 * j + 1]);
            __half2 h1 = __floats2half2_rn(wv[4 * j + 2], wv[4 * j + 3]);
            d.x = *reinterpret_cast<uint32_t*>(&h0);
            d.y = *reinterpret_cast<uint32_t*>(&h1);
            *reinterpret_cast<uint2*>(sb + rowbase + j * 8) = d;
        }
    }
    __syncthreads();

    // --- MMA: warp w = m-tile w; 20 n-tiles; 2 k-chunks ---
    float c[20][4];
#pragma unroll
    for (int nt = 0; nt < 20; nt++)
#pragma unroll
        for (int q = 0; q < 4; q++) c[nt][q] = 0.f;

#pragma unroll
    for (int kc = 0; kc < 2; kc++) {
        const int abase = A_OFF + (wid * 16 + gid) * SA + tig * 4 + kc * 32;
        const uint32_t a0 = *reinterpret_cast<const uint32_t*>(sb + abase);
        const uint32_t a1 = *reinterpret_cast<const uint32_t*>(sb + abase + 8 * SA);
        const uint32_t a2 = *reinterpret_cast<const uint32_t*>(sb + abase + 16);
        const uint32_t a3 = *reinterpret_cast<const uint32_t*>(sb + abase + 8 * SA + 16);
#pragma unroll
        for (int nt = 0; nt < 20; nt++) {
            const int bbase = BOFF + (nt * 8 + gid) * SA + tig * 4 + kc * 32;
            const uint32_t b0 = *reinterpret_cast<const uint32_t*>(sb + bbase);
            const uint32_t b1 = *reinterpret_cast<const uint32_t*>(sb + bbase + 16);
            mma16816(c[nt], a0, a1, a2, a3, b0, b1);
        }
    }
    __syncthreads();   // A/B reads done; smem reused as staging

    // --- Stage D as fp16 ---
    const int r0 = wid * 16 + gid;
#pragma unroll
    for (int nt = 0; nt < 20; nt++) {
        const int cb = (nt * 8 + tig * 2) * 2;
        __half2 h0 = __floats2half2_rn(c[nt][0], c[nt][1]);
        __half2 h1 = __floats2half2_rn(c[nt][2], c[nt][3]);
        *reinterpret_cast<uint32_t*>(sb + r0 * SSTG + cb) =
            *reinterpret_cast<uint32_t*>(&h0);
        *reinterpret_cast<uint32_t*>(sb + (r0 + 8) * SSTG + cb) =
            *reinterpret_cast<uint32_t*>(&h1);
    }
    __syncthreads();

    // --- Coalesced flush: 2560 uint4 ---
#pragma unroll
    for (int it = 0; it < 10; it++) {
        const int idx = it * 256 + tid;
        const int row = idx / 20, col = idx % 20;
        reinterpret_cast<uint4*>(g_u + ((size_t)row * P_ + p) * K_)[col] =
            *reinterpret_cast<const uint4*>(sb + row * SSTG + col * 16);
    }
}

// ---------------------------------------------------------------------------
// Shared epilogue: last block for a given b squashes g_s.
// MODE 0: g_v = squash(s), zero s. MODE 1: g_v += squash(s), zero s
// (g_v becomes v0+v1 -> bias-free iter-2 logit). MODE 2: out = squash(s).
// ---------------------------------------------------------------------------
template <int MODE>
__device__ __forceinline__ void epilogue(int b, int tid, float* __restrict__ out) {
    __shared__ int s_done;
    __threadfence();
    __syncthreads();
    if (tid == 0)
        s_done = (atomicAdd(&g_cnt[b], 1) == RT_BLOCKS_PER_B - 1) ? 1 : 0;
    __syncthreads();
    if (!s_done) return;
    __threadfence();
    if (tid < K_) {
        const float sv = __ldcg(&g_s[b * K_ + tid]);
        float ss = sv * sv;
        ss += __shfl_xor_sync(0xffffffffu, ss, 1);
        ss += __shfl_xor_sync(0xffffffffu, ss, 2);
        ss += __shfl_xor_sync(0xffffffffu, ss, 4);
        ss += __shfl_xor_sync(0xffffffffu, ss, 8);
        const float scale = ss / ((1.f + ss) * sqrtf(ss));
        const float vv = sv * scale;
        if (MODE == 0) {
            g_v[b * K_ + tid] = vv;
            g_s[b * K_ + tid] = 0.f;
        } else if (MODE == 1) {
            g_v[b * K_ + tid] += vv;
            g_s[b * K_ + tid] = 0.f;
        } else {
            out[b * K_ + tid] = vv;
        }
    }
    if (tid == 0) g_cnt[b] = 0;
}

// ---------------------------------------------------------------------------
// Iter 0: s0 = (1/NC) * sum_p u[b,p,:]. Fully coalesced uint4 reads.
// 160 threads: chunk=tid%20, sub=tid/20 -> 8 stripes of 16 p; 128 p/block.
// ---------------------------------------------------------------------------
__global__ __launch_bounds__(160) void k_sum0() {
    const int b = blockIdx.y;
    const int tid = threadIdx.x;
    const int chunk = tid % 20;
    const int sub = tid / 20;
    const int p0 = blockIdx.x * 128 + sub * 16;

    float acc[8];
#pragma unroll
    for (int j = 0; j < 8; j++) acc[j] = 0.f;

#pragma unroll
    for (int i = 0; i < 16; i++) {
        const uint4 q = reinterpret_cast<const uint4*>(
            g_u + ((size_t)b * P_ + p0 + i) * K_)[chunk];
        const __half2* h = reinterpret_cast<const __half2*>(&q);
#pragma unroll
        for (int j = 0; j < 4; j++) {
            float2 f = __half22float2(h[j]);
            acc[2 * j] += f.x;
            acc[2 * j + 1] += f.y;
        }
    }

    __shared__ float s_red[8][K_];
#pragma unroll
    for (int j = 0; j < 8; j++) s_red[sub][chunk * 8 + j] = acc[j];
    __syncthreads();
    if (tid < K_) {
        float s = 0.f;
#pragma unroll
        for (int w = 0; w < 8; w++) s += s_red[w][tid];
        atomicAdd(&g_s[b * K_ + tid], s * (1.0f / NC_));
    }
    epilogue<0>(b, tid, nullptr);
}

// ---------------------------------------------------------------------------
// Routing pass (iters 1 and 2). Thread = (p, n); each 16-lane group
// processes TWO p's per j-step with independent register chains.
// ---------------------------------------------------------------------------
template <bool LAST>
__global__ __launch_bounds__(RT_THREADS) void k_route(float* __restrict__ out) {
    const int b   = blockIdx.y;
    const int tid = threadIdx.x;
    const int grp = tid >> 4;
    const int gl  = tid & 15;
    const int nn  = (gl < NC_) ? gl : 0;
    const bool act = (gl < NC_);
    const int warp = tid >> 5, lane = tid & 31;

    // v (loop-invariant) packed as half2
    __half2 vh[8];
    {
        const float4* vp = reinterpret_cast<const float4*>(g_v + b * K_ + nn * 16);
#pragma unroll
        for (int q = 0; q < 4; q++) {
            float4 t = vp[q];
            vh[2 * q]     = __floats2half2_rn(t.x, t.y);
            vh[2 * q + 1] = __floats2half2_rn(t.z, t.w);
        }
    }

    unsigned long long acc2[8];
#pragma unroll
    for (int i = 0; i < 8; i++) acc2[i] = 0ull;

    const int p_base = blockIdx.x * 128;
#pragma unroll
    for (int j = 0; j < 4; j++) {
        const int p0 = p_base + (2 * j) * 16 + grp;
        const int p1 = p_base + (2 * j + 1) * 16 + grp;

        uint4 qa0 = make_uint4(0, 0, 0, 0), qa1 = qa0, qb0 = qa0, qb1 = qa0;
        if (act) {
            const uint4* ua = reinterpret_cast<const uint4*>(
                g_u + ((size_t)b * P_ + p0) * K_ + nn * 16);
            const uint4* ub = reinterpret_cast<const uint4*>(
                g_u + ((size_t)b * P_ + p1) * K_ + nn * 16);
            qa0 = ua[0]; qa1 = ua[1];
            qb0 = ub[0]; qb1 = ub[1];
        }
        __half2 uha[8], uhb[8];
        {
            const __half2* a0 = reinterpret_cast<const __half2*>(&qa0);
            const __half2* a1 = reinterpret_cast<const __half2*>(&qa1);
            const __half2* b0 = reinterpret_cast<const __half2*>(&qb0);
            const __half2* b1 = reinterpret_cast<const __half2*>(&qb1);
#pragma unroll
            for (int i = 0; i < 4; i++) {
                uha[i] = a0[i]; uha[4 + i] = a1[i];
                uhb[i] = b0[i]; uhb[4 + i] = b1[i];
            }
        }

        // two independent logit dots (HFMA2, fp32 finish)
        __half2 dha = __hmul2(uha[0], vh[0]);
        __half2 dhb = __hmul2(uhb[0], vh[0]);
#pragma unroll
        for (int i = 1; i < 8; i++) {
            dha = __hfma2(uha[i], vh[i], dha);
            dhb = __hfma2(uhb[i], vh[i], dhb);
        }
        float2 dfa = __half22float2(dha);
        float2 dfb = __half22float2(dhb);
        const float da = dfa.x + dfa.y;
        const float db = dfb.x + dfb.y;

        // two interleaved softmax reductions (no max: logits bounded)
        float ea = act ? __expf(da) : 0.f;
        float eb = act ? __expf(db) : 0.f;
        float dena = ea, denb = eb;
        dena += __shfl_xor_sync(0xffffffffu, dena, 1);
        denb += __shfl_xor_sync(0xffffffffu, denb, 1);
        dena += __shfl_xor_sync(0xffffffffu, dena, 2);
        denb += __shfl_xor_sync(0xffffffffu, denb, 2);
        dena += __shfl_xor_sync(0xffffffffu, dena, 4);
        denb += __shfl_xor_sync(0xffffffffu, denb, 4);
        dena += __shfl_xor_sync(0xffffffffu, dena, 8);
        denb += __shfl_xor_sync(0xffffffffu, denb, 8);
        const float ca = ea / dena;
        const float cb = eb / denb;

        const unsigned long long ca2 = pack2(ca, ca);
        const unsigned long long cb2 = pack2(cb, cb);
#pragma unroll
        for (int i = 0; i < 8; i++) {
            float2 ufa = __half22float2(uha[i]);
            float2 ufb = __half22float2(uhb[i]);
            fma2(acc2[i], ca2, pack2(ufa.x, ufa.y));
            fma2(acc2[i], cb2, pack2(ufb.x, ufb.y));
        }
    }

    float acc[16];
#pragma unroll
    for (int i = 0; i < 8; i++) unpack2(acc2[i], acc[2 * i], acc[2 * i + 1]);

    // combine the two 16-lane groups (same (n,k), different p)
#pragma unroll
    for (int k = 0; k < 16; k++)
        acc[k] += __shfl_xor_sync(0xffffffffu, acc[k], 16);

    __shared__ float s_red[RT_THREADS / 32][K_];
    if (lane < 16 && act) {
#pragma unroll
        for (int k = 0; k < 16; k++) s_red[warp][nn * 16 + k] = acc[k];
    }
    __syncthreads();
    if (tid < K_) {
        float s = 0.f;
#pragma unroll
        for (int w = 0; w < RT_THREADS / 32; w++) s += s_red[w][tid];
        atomicAdd(&g_s[b * K_ + tid], s);
    }
    epilogue<LAST ? 2 : 1>(b, tid, out);
}

// ---------------------------------------------------------------------------
extern "C" void kernel_launch(void* const* d_in, const int* in_sizes, int n_in,
                              void* d_out, int out_size) {
    const float* tensor = (const float*)d_in[0];
    const float* weight = (const float*)d_in[1];
    float* out = (float*)d_out;

    k1_mma<<<P_, 256>>>(tensor, weight);

    dim3 rg(RT_BLOCKS_PER_B, B_);
    k_sum0<<<rg, 160>>>();                       // iter 0 (uniform c) + squash
    k_route<false><<<rg, RT_THREADS>>>(nullptr); // iter 1; g_v <- v0+v1
    k_route<true ><<<rg, RT_THREADS>>>(out);     // iter 2; emit output
}

// round 13
// speedup vs baseline: 2.9551x; 1.0145x over previous
#include <cuda_runtime.h>
#include <cuda_fp16.h>
#include <math.h>
#include <stdint.h>

// Problem constants
#define B_    128
#define P_    2048      // CL*H*W
#define NP_   32
#define NC_   10
#define K_    160       // NC_*CLO_

// Route geometry: 16 blocks per batch, 128 p per block
#define RT_BLOCKS_PER_B 16
#define RT_THREADS 256

// Scratch (allocation-free device globals; zero-initialized)
__device__ __align__(32) __half g_u[(size_t)B_ * P_ * K_];  // 83.9 MB, lives in L2
__device__ float  g_s[B_ * K_];
__device__ float  g_v[B_ * K_];
__device__ int    g_cnt[B_];                    // self-resetting completion counters

// ---------------------------------------------------------------------------
// L2 eviction-priority helpers. sm_103 ptxas: evict_last requires 256-bit
// (v4.b64) for BOTH ld and st. Streaming inputs use __ldcs.
// ---------------------------------------------------------------------------
__device__ __forceinline__ void ldg_el_32B(const void* p, uint4& q0, uint4& q1) {
    unsigned long long a, b, c, d;
    asm volatile("ld.global.nc.L2::evict_last.v4.b64 {%0,%1,%2,%3}, [%4];"
                 : "=l"(a), "=l"(b), "=l"(c), "=l"(d) : "l"(p));
    q0.x = (uint32_t)a; q0.y = (uint32_t)(a >> 32);
    q0.z = (uint32_t)b; q0.w = (uint32_t)(b >> 32);
    q1.x = (uint32_t)c; q1.y = (uint32_t)(c >> 32);
    q1.z = (uint32_t)d; q1.w = (uint32_t)(d >> 32);
}
__device__ __forceinline__ void stg_el_32B(void* p, uint4 v0, uint4 v1) {
    unsigned long long a = (unsigned long long)v0.x | ((unsigned long long)v0.y << 32);
    unsigned long long b = (unsigned long long)v0.z | ((unsigned long long)v0.w << 32);
    unsigned long long c = (unsigned long long)v1.x | ((unsigned long long)v1.y << 32);
    unsigned long long d = (unsigned long long)v1.z | ((unsigned long long)v1.w << 32);
    asm volatile("st.global.L2::evict_last.v4.b64 [%0], {%1,%2,%3,%4};"
                 :: "l"(p), "l"(a), "l"(b), "l"(c), "l"(d) : "memory");
}

// ---------------------------------------------------------------------------
// Packed f32x2 helpers (route)
// ---------------------------------------------------------------------------
__device__ __forceinline__ unsigned long long pack2(float lo, float hi) {
    unsigned long long r;
    asm("mov.b64 %0, {%1, %2};" : "=l"(r) : "f"(lo), "f"(hi));
    return r;
}
__device__ __forceinline__ void unpack2(unsigned long long v, float& lo, float& hi) {
    asm("mov.b64 {%0, %1}, %2;" : "=f"(lo), "=f"(hi) : "l"(v));
}
__device__ __forceinline__ void fma2(unsigned long long& d,
                                     unsigned long long a,
                                     unsigned long long b) {
    asm("fma.rn.f32x2 %0, %1, %2, %0;" : "+l"(d) : "l"(a), "l"(b));
}

// ---------------------------------------------------------------------------
// K1 (HMMA): per p, D[128 b][160 t] = squash(x)[128 b][32 n] @ W[32 n][160 t]
// via mma.sync.m16n8k16 (fp16 in, fp32 acc). 256 threads = 8 warps.
// Inputs read with __ldcs (streaming); u flushed with 256-bit evict_last.
// ---------------------------------------------------------------------------
#define SA 80
#define A_OFF 0                       // 128*80 = 10240
#define BOFF  10240                   // 160*80 = 12800, ends 23040
#define SSTG  336
#define SB_BYTES (128 * SSTG)         // 43008 (union covers A+B = 23040)

__device__ __forceinline__ void mma16816(float* c, uint32_t a0, uint32_t a1,
                                         uint32_t a2, uint32_t a3,
                                         uint32_t b0, uint32_t b1) {
    asm volatile(
        "mma.sync.aligned.m16n8k16.row.col.f32.f16.f16.f32 "
        "{%0,%1,%2,%3}, {%4,%5,%6,%7}, {%8,%9}, {%0,%1,%2,%3};"
        : "+f"(c[0]), "+f"(c[1]), "+f"(c[2]), "+f"(c[3])
        : "r"(a0), "r"(a1), "r"(a2), "r"(a3), "r"(b0), "r"(b1));
}

__global__ __launch_bounds__(256) void k1_mma(
    const float* __restrict__ tensor, const float* __restrict__ weight) {
    const int p = blockIdx.x;
    const int tid = threadIdx.x;
    const int wid = tid >> 5;
    const int lane = tid & 31;
    const int gid = lane >> 2;    // 0..7
    const int tig = lane & 3;     // 0..3

    __shared__ __align__(16) unsigned char sb[SB_BYTES];

    if (p == 0) {
        for (int i = tid; i < B_ * K_; i += 256) g_s[i] = 0.f;
    }

    // --- A fill: warp w rows b = 16w+i; lane = n. squash inline. ---
    const float* xbase = tensor + (size_t)p * NP_;
#pragma unroll
    for (int i = 0; i < 16; i++) {
        const int b = wid * 16 + i;
        const float x = __ldcs(xbase + (size_t)b * P_ * NP_ + lane);
        float ss = x * x;
        ss += __shfl_xor_sync(0xffffffffu, ss, 1);
        ss += __shfl_xor_sync(0xffffffffu, ss, 2);
        ss += __shfl_xor_sync(0xffffffffu, ss, 4);
        ss += __shfl_xor_sync(0xffffffffu, ss, 8);
        ss += __shfl_xor_sync(0xffffffffu, ss, 16);
        const float scale = ss / ((1.f + ss) * sqrtf(ss));
        *reinterpret_cast<__half*>(sb + A_OFF + b * SA + lane * 2) =
            __float2half(x * scale);
    }

    // --- B fill: thread owns row t (t=tid<160): Bt[t][k] = W[k][t]. ---
    const float* wbase = weight + (size_t)p * NP_ * K_;
    if (tid < K_) {
        float wv[NP_];
#pragma unroll
        for (int n = 0; n < NP_; n++) wv[n] = __ldcs(wbase + (size_t)n * K_ + tid);
        const int rowbase = BOFF + tid * SA;
#pragma unroll
        for (int j = 0; j < 8; j++) {
            uint2 d;
            __half2 h0 = __floats2half2_rn(wv[4 * j], wv[4 * j + 1]);
            __half2 h1 = __floats2half2_rn(wv[4 * j + 2], wv[4 * j + 3]);
            d.x = *reinterpret_cast<uint32_t*>(&h0);
            d.y = *reinterpret_cast<uint32_t*>(&h1);
            *reinterpret_cast<uint2*>(sb + rowbase + j * 8) = d;
        }
    }
    __syncthreads();

    // --- MMA: warp w = m-tile w; 20 n-tiles; 2 k-chunks ---
    float c[20][4];
#pragma unroll
    for (int nt = 0; nt < 20; nt++)
#pragma unroll
        for (int q = 0; q < 4; q++) c[nt][q] = 0.f;

#pragma unroll
    for (int kc = 0; kc < 2; kc++) {
        const int abase = A_OFF + (wid * 16 + gid) * SA + tig * 4 + kc * 32;
        const uint32_t a0 = *reinterpret_cast<const uint32_t*>(sb + abase);
        const uint32_t a1 = *reinterpret_cast<const uint32_t*>(sb + abase + 8 * SA);
        const uint32_t a2 = *reinterpret_cast<const uint32_t*>(sb + abase + 16);
        const uint32_t a3 = *reinterpret_cast<const uint32_t*>(sb + abase + 8 * SA + 16);
#pragma unroll
        for (int nt = 0; nt < 20; nt++) {
            const int bbase = BOFF + (nt * 8 + gid) * SA + tig * 4 + kc * 32;
            const uint32_t b0 = *reinterpret_cast<const uint32_t*>(sb + bbase);
            const uint32_t b1 = *reinterpret_cast<const uint32_t*>(sb + bbase + 16);
            mma16816(c[nt], a0, a1, a2, a3, b0, b1);
        }
    }
    __syncthreads();   // A/B reads done; smem reused as staging

    // --- Stage D as fp16 ---
    const int r0 = wid * 16 + gid;
#pragma unroll
    for (int nt = 0; nt < 20; nt++) {
        const int cb = (nt * 8 + tig * 2) * 2;
        __half2 h0 = __floats2half2_rn(c[nt][0], c[nt][1]);
        __half2 h1 = __floats2half2_rn(c[nt][2], c[nt][3]);
        *reinterpret_cast<uint32_t*>(sb + r0 * SSTG + cb) =
            *reinterpret_cast<uint32_t*>(&h0);
        *reinterpret_cast<uint32_t*>(sb + (r0 + 8) * SSTG + cb) =
            *reinterpret_cast<uint32_t*>(&h1);
    }
    __syncthreads();

    // --- Coalesced flush with 256-bit evict_last: 1280 chunks of 32B ---
#pragma unroll
    for (int it = 0; it < 5; it++) {
        const int idx = it * 256 + tid;
        const int row = idx / 10, col = idx % 10;     // col = 32B chunk in row
        const uint4* s = reinterpret_cast<const uint4*>(sb + row * SSTG + col * 32);
        stg_el_32B(reinterpret_cast<char*>(g_u + ((size_t)row * P_ + p) * K_) + col * 32,
                   s[0], s[1]);
    }
}

// ---------------------------------------------------------------------------
// Shared epilogue: last block for a given b squashes g_s.
// MODE 0: g_v = squash(s), zero s. MODE 1: g_v += squash(s), zero s
// (g_v becomes v0+v1 -> bias-free iter-2 logit). MODE 2: out = squash(s).
// ---------------------------------------------------------------------------
template <int MODE>
__device__ __forceinline__ void epilogue(int b, int tid, float* __restrict__ out) {
    __shared__ int s_done;
    __threadfence();
    __syncthreads();
    if (tid == 0)
        s_done = (atomicAdd(&g_cnt[b], 1) == RT_BLOCKS_PER_B - 1) ? 1 : 0;
    __syncthreads();
    if (!s_done) return;
    __threadfence();
    if (tid < K_) {
        const float sv = __ldcg(&g_s[b * K_ + tid]);
        float ss = sv * sv;
        ss += __shfl_xor_sync(0xffffffffu, ss, 1);
        ss += __shfl_xor_sync(0xffffffffu, ss, 2);
        ss += __shfl_xor_sync(0xffffffffu, ss, 4);
        ss += __shfl_xor_sync(0xffffffffu, ss, 8);
        const float scale = ss / ((1.f + ss) * sqrtf(ss));
        const float vv = sv * scale;
        if (MODE == 0) {
            g_v[b * K_ + tid] = vv;
            g_s[b * K_ + tid] = 0.f;
        } else if (MODE == 1) {
            g_v[b * K_ + tid] += vv;
            g_s[b * K_ + tid] = 0.f;
        } else {
            out[b * K_ + tid] = vv;
        }
    }
    if (tid == 0) g_cnt[b] = 0;
}

// ---------------------------------------------------------------------------
// Iter 0: s0 = (1/NC) * sum_p u[b,p,:]. Fully coalesced uint4 reads
// (L2 hits — lines pinned by k1's evict_last stores).
// 160 threads: chunk=tid%20, sub=tid/20 -> 8 stripes of 16 p; 128 p/block.
// ---------------------------------------------------------------------------
__global__ __launch_bounds__(160) void k_sum0() {
    const int b = blockIdx.y;
    const int tid = threadIdx.x;
    const int chunk = tid % 20;
    const int sub = tid / 20;
    const int p0 = blockIdx.x * 128 + sub * 16;

    float acc[8];
#pragma unroll
    for (int j = 0; j < 8; j++) acc[j] = 0.f;

#pragma unroll
    for (int i = 0; i < 16; i++) {
        const uint4 q = reinterpret_cast<const uint4*>(
            g_u + ((size_t)b * P_ + p0 + i) * K_)[chunk];
        const __half2* h = reinterpret_cast<const __half2*>(&q);
#pragma unroll
        for (int j = 0; j < 4; j++) {
            float2 f = __half22float2(h[j]);
            acc[2 * j] += f.x;
            acc[2 * j + 1] += f.y;
        }
    }

    __shared__ float s_red[8][K_];
#pragma unroll
    for (int j = 0; j < 8; j++) s_red[sub][chunk * 8 + j] = acc[j];
    __syncthreads();
    if (tid < K_) {
        float s = 0.f;
#pragma unroll
        for (int w = 0; w < 8; w++) s += s_red[w][tid];
        atomicAdd(&g_s[b * K_ + tid], s * (1.0f / NC_));
    }
    epilogue<0>(b, tid, nullptr);
}

// ---------------------------------------------------------------------------
// Routing pass (iters 1 and 2). Thread = (p, n); each 16-lane group
// processes TWO p's per j-step with independent register chains.
// u row (32B, aligned) loaded as one 256-bit evict_last LDG.
// ---------------------------------------------------------------------------
template <bool LAST>
__global__ __launch_bounds__(RT_THREADS) void k_route(float* __restrict__ out) {
    const int b   = blockIdx.y;
    const int tid = threadIdx.x;
    const int grp = tid >> 4;
    const int gl  = tid & 15;
    const int nn  = (gl < NC_) ? gl : 0;
    const bool act = (gl < NC_);
    const int warp = tid >> 5, lane = tid & 31;

    // v (loop-invariant) packed as half2
    __half2 vh[8];
    {
        const float4* vp = reinterpret_cast<const float4*>(g_v + b * K_ + nn * 16);
#pragma unroll
        for (int q = 0; q < 4; q++) {
            float4 t = vp[q];
            vh[2 * q]     = __floats2half2_rn(t.x, t.y);
            vh[2 * q + 1] = __floats2half2_rn(t.z, t.w);
        }
    }

    unsigned long long acc2[8];
#pragma unroll
    for (int i = 0; i < 8; i++) acc2[i] = 0ull;

    const int p_base = blockIdx.x * 128;
#pragma unroll
    for (int j = 0; j < 4; j++) {
        const int p0 = p_base + (2 * j) * 16 + grp;
        const int p1 = p_base + (2 * j + 1) * 16 + grp;

        uint4 qa0 = make_uint4(0, 0, 0, 0), qa1 = qa0, qb0 = qa0, qb1 = qa0;
        if (act) {
            ldg_el_32B(g_u + ((size_t)b * P_ + p0) * K_ + nn * 16, qa0, qa1);
            ldg_el_32B(g_u + ((size_t)b * P_ + p1) * K_ + nn * 16, qb0, qb1);
        }
        __half2 uha[8], uhb[8];
        {
            const __half2* a0 = reinterpret_cast<const __half2*>(&qa0);
            const __half2* a1 = reinterpret_cast<const __half2*>(&qa1);
            const __half2* b0 = reinterpret_cast<const __half2*>(&qb0);
            const __half2* b1 = reinterpret_cast<const __half2*>(&qb1);
#pragma unroll
            for (int i = 0; i < 4; i++) {
                uha[i] = a0[i]; uha[4 + i] = a1[i];
                uhb[i] = b0[i]; uhb[4 + i] = b1[i];
            }
        }

        // two independent logit dots (HFMA2, fp32 finish)
        __half2 dha = __hmul2(uha[0], vh[0]);
        __half2 dhb = __hmul2(uhb[0], vh[0]);
#pragma unroll
        for (int i = 1; i < 8; i++) {
            dha = __hfma2(uha[i], vh[i], dha);
            dhb = __hfma2(uhb[i], vh[i], dhb);
        }
        float2 dfa = __half22float2(dha);
        float2 dfb = __half22float2(dhb);
        const float da = dfa.x + dfa.y;
        const float db = dfb.x + dfb.y;

        // two interleaved softmax reductions (no max: logits bounded)
        float ea = act ? __expf(da) : 0.f;
        float eb = act ? __expf(db) : 0.f;
        float dena = ea, denb = eb;
        dena += __shfl_xor_sync(0xffffffffu, dena, 1);
        denb += __shfl_xor_sync(0xffffffffu, denb, 1);
        dena += __shfl_xor_sync(0xffffffffu, dena, 2);
        denb += __shfl_xor_sync(0xffffffffu, denb, 2);
        dena += __shfl_xor_sync(0xffffffffu, dena, 4);
        denb += __shfl_xor_sync(0xffffffffu, denb, 4);
        dena += __shfl_xor_sync(0xffffffffu, dena, 8);
        denb += __shfl_xor_sync(0xffffffffu, denb, 8);
        const float ca = ea / dena;
        const float cb = eb / denb;

        const unsigned long long ca2 = pack2(ca, ca);
        const unsigned long long cb2 = pack2(cb, cb);
#pragma unroll
        for (int i = 0; i < 8; i++) {
            float2 ufa = __half22float2(uha[i]);
            float2 ufb = __half22float2(uhb[i]);
            fma2(acc2[i], ca2, pack2(ufa.x, ufa.y));
            fma2(acc2[i], cb2, pack2(ufb.x, ufb.y));
        }
    }

    float acc[16];
#pragma unroll
    for (int i = 0; i < 8; i++) unpack2(acc2[i], acc[2 * i], acc[2 * i + 1]);

    // combine the two 16-lane groups (same (n,k), different p)
#pragma unroll
    for (int k = 0; k < 16; k++)
        acc[k] += __shfl_xor_sync(0xffffffffu, acc[k], 16);

    __shared__ float s_red[RT_THREADS / 32][K_];
    if (lane < 16 && act) {
#pragma unroll
        for (int k = 0; k < 16; k++) s_red[warp][nn * 16 + k] = acc[k];
    }
    __syncthreads();
    if (tid < K_) {
        float s = 0.f;
#pragma unroll
        for (int w = 0; w < RT_THREADS / 32; w++) s += s_red[w][tid];
        atomicAdd(&g_s[b * K_ + tid], s);
    }
    epilogue<LAST ? 2 : 1>(b, tid, out);
}

// ---------------------------------------------------------------------------
extern "C" void kernel_launch(void* const* d_in, const int* in_sizes, int n_in,
                              void* d_out, int out_size) {
    const float* tensor = (const float*)d_in[0];
    const float* weight = (const float*)d_in[1];
    float* out = (float*)d_out;

    k1_mma<<<P_, 256>>>(tensor, weight);

    dim3 rg(RT_BLOCKS_PER_B, B_);
    k_sum0<<<rg, 160>>>();                       // iter 0 (uniform c) + squash
    k_route<false><<<rg, RT_THREADS>>>(nullptr); // iter 1; g_v <- v0+v1
    k_route<true ><<<rg, RT_THREADS>>>(out);     // iter 2; emit output
}